// round 1
// baseline (speedup 1.0000x reference)
#include <cuda_runtime.h>
#include <math.h>

// Problem constants
#define D_IN   512
#define HID    1024          // 2*D_IN
#define SEQ    4096
#define BATCH  4
#define CHUNK  256
#define NCHUNK 16
#define ROWS_TOTAL (BATCH*SEQ)     // 16384
#define ROWS_CHUNK (BATCH*CHUNK)   // 1024
#define WSZ    (D_IN*HID)          // 524288

// ---------------- scratch (device globals; no allocation allowed) ----------
__device__ float g_Q [ROWS_TOTAL*D_IN];
__device__ float g_K [ROWS_TOTAL*D_IN];   // chunk-major: [c][b][t][d]
__device__ float g_V [ROWS_TOTAL*D_IN];   // chunk-major
__device__ float g_W1[WSZ];
__device__ float g_W2[WSZ];
__device__ float g_S1[WSZ];
__device__ float g_S2[WSZ];
__device__ float g_H [ROWS_CHUNK*HID];
__device__ float g_A [ROWS_CHUNK*HID];
__device__ float g_dH[ROWS_CHUNK*HID];
__device__ float g_E [ROWS_CHUNK*D_IN];
__device__ float g_G1[WSZ];
__device__ float g_G2[WSZ];
__device__ float g_Hq[ROWS_TOTAL*HID];

// ---------------- math helpers --------------------------------------------
__device__ __forceinline__ float gelu_f(float x) {
    return 0.5f * x * (1.0f + erff(x * 0.70710678118654752f));
}
__device__ __forceinline__ float gelu_grad_f(float x) {
    float cdf = 0.5f * (1.0f + erff(x * 0.70710678118654752f));
    float pdf = 0.3989422804014327f * __expf(-0.5f * x * x);
    return cdf + x * pdf;
}
__device__ __forceinline__ float sigmoid_f(float x) {
    return 1.0f / (1.0f + __expf(-x));
}

// ---------------- generic tiled fp32 GEMM ----------------------------------
// C[M,N] = op(A) @ op(B), 64x64 tile, BK=16, 4x4 microtile, 256 threads.
// TA: A stored [K,M] (lda = M stride), element (m,k) at A[k*lda+m]
// TB: B stored [N,K] (ldb = K stride), element (k,n) at B[n*ldb+k]
// All M,N multiples of 64; K multiple of 16 (guaranteed by the problem).
//
// EPI: 0 = C = acc
//      1 = C = acc, out2 = gelu(acc)
//      2 = C = (acc - aux[idx]) * scale
//      3 = C = acc * gelu'(aux[idx])
//      4 = C = gelu(acc)
//      5 = chunk-permuted store (for K/V):   m = b*4096+s -> row c*1024+b*256+t
template<bool TA, bool TB, int EPI>
__global__ void __launch_bounds__(256)
gemm64(const float* __restrict__ A, int lda,
       const float* __restrict__ B, int ldb,
       float* __restrict__ C, int ldc,
       int K,
       const float* __restrict__ aux, float* __restrict__ out2, float scale)
{
    __shared__ float As[16][68];   // padded: 2-way max conflicts, rows 16B aligned
    __shared__ float Bs[16][68];

    const int tid = threadIdx.x;
    const int m0 = blockIdx.y * 64;
    const int n0 = blockIdx.x * 64;
    const int ty = tid >> 4;       // 0..15  -> rows m0+ty*4 .. +3
    const int tx = tid & 15;       // 0..15  -> cols n0+tx*4 .. +3

    float acc[4][4] = {};

    for (int k0 = 0; k0 < K; k0 += 16) {
        // ---- load A tile into As[k][m] ----
        if (!TA) {
            int e = tid;
            #pragma unroll
            for (int i = 0; i < 4; i++) {
                int r = e >> 4, c = e & 15;           // r=m-local, c=k-local
                As[c][r] = A[(size_t)(m0 + r) * lda + (k0 + c)];
                e += 256;
            }
        } else {
            int e = tid;
            #pragma unroll
            for (int i = 0; i < 4; i++) {
                int r = e >> 6, c = e & 63;           // r=k-local, c=m-local
                As[r][c] = A[(size_t)(k0 + r) * lda + (m0 + c)];
                e += 256;
            }
        }
        // ---- load B tile into Bs[k][n] ----
        if (!TB) {
            int e = tid;
            #pragma unroll
            for (int i = 0; i < 4; i++) {
                int r = e >> 6, c = e & 63;           // r=k-local, c=n-local
                Bs[r][c] = B[(size_t)(k0 + r) * ldb + (n0 + c)];
                e += 256;
            }
        } else {
            int e = tid;
            #pragma unroll
            for (int i = 0; i < 4; i++) {
                int r = e >> 4, c = e & 15;           // r=n-local, c=k-local
                Bs[c][r] = B[(size_t)(n0 + r) * ldb + (k0 + c)];
                e += 256;
            }
        }
        __syncthreads();

        #pragma unroll
        for (int kk = 0; kk < 16; kk++) {
            float4 a4 = *(const float4*)&As[kk][ty * 4];
            float4 b4 = *(const float4*)&Bs[kk][tx * 4];
            float av[4] = {a4.x, a4.y, a4.z, a4.w};
            float bv[4] = {b4.x, b4.y, b4.z, b4.w};
            #pragma unroll
            for (int i = 0; i < 4; i++)
                #pragma unroll
                for (int j = 0; j < 4; j++)
                    acc[i][j] = fmaf(av[i], bv[j], acc[i][j]);
        }
        __syncthreads();
    }

    // ---- epilogue ----
    #pragma unroll
    for (int i = 0; i < 4; i++) {
        int m = m0 + ty * 4 + i;
        #pragma unroll
        for (int j = 0; j < 4; j++) {
            int n = n0 + tx * 4 + j;
            float v = acc[i][j];
            size_t idx = (size_t)m * ldc + n;
            if (EPI == 0) {
                C[idx] = v;
            } else if (EPI == 1) {
                C[idx] = v;
                out2[idx] = gelu_f(v);
            } else if (EPI == 2) {
                C[idx] = (v - aux[idx]) * scale;
            } else if (EPI == 3) {
                C[idx] = v * gelu_grad_f(aux[idx]);
            } else if (EPI == 4) {
                C[idx] = gelu_f(v);
            } else { // EPI == 5: permuted chunk-major store
                int b = m >> 12;          // /4096
                int s = m & 4095;
                int cc = s >> 8;          // /256
                int t = s & 255;
                int orow = cc * 1024 + b * 256 + t;
                C[(size_t)orow * ldc + n] = v;
            }
        }
    }
}

// ---------------- init: W <- mem_w, S <- 0 ---------------------------------
__global__ void init_kernel(const float* __restrict__ w1, const float* __restrict__ w2) {
    int i = blockIdx.x * 256 + threadIdx.x;
    if (i < WSZ) {
        g_W1[i] = w1[i];
        g_W2[i] = w2[i];
        g_S1[i] = 0.0f;
        g_S2[i] = 0.0f;
    }
}

// ---------------- momentum + weight-decay update ---------------------------
__global__ void update_kernel(const float* __restrict__ alpha_t,
                              const float* __restrict__ lr_t,
                              const float* __restrict__ decay_t,
                              const int*  __restrict__ update_mem) {
    if (*update_mem == 0) return;
    int i = blockIdx.x * 256 + threadIdx.x;
    if (i >= WSZ) return;
    float alpha = sigmoid_f(*alpha_t);
    float lr    = sigmoid_f(*lr_t);
    float decay = sigmoid_f(*decay_t);
    float om = 1.0f - alpha;

    float s1 = decay * g_S1[i] - lr * g_G1[i];
    g_S1[i] = s1;
    g_W1[i] = om * g_W1[i] + s1;

    float s2 = decay * g_S2[i] - lr * g_G2[i];
    g_S2[i] = s2;
    g_W2[i] = om * g_W2[i] + s2;
}

// ---------------- launcher --------------------------------------------------
extern "C" void kernel_launch(void* const* d_in, const int* in_sizes, int n_in,
                              void* d_out, int out_size)
{
    const float* x        = (const float*)d_in[0];
    const float* w_q      = (const float*)d_in[1];
    const float* w_k      = (const float*)d_in[2];
    const float* w_v      = (const float*)d_in[3];
    const float* mem_w1   = (const float*)d_in[4];
    const float* mem_w2   = (const float*)d_in[5];
    const float* alpha_t  = (const float*)d_in[6];
    const float* lr_t     = (const float*)d_in[7];
    const float* decay_t  = (const float*)d_in[8];
    const int*   upd      = (const int*)d_in[9];
    float* out = (float*)d_out;

    float *Q, *K, *V, *W1, *W2, *H, *A, *dH, *E, *G1, *G2, *Hq;
    cudaGetSymbolAddress((void**)&Q,  g_Q);
    cudaGetSymbolAddress((void**)&K,  g_K);
    cudaGetSymbolAddress((void**)&V,  g_V);
    cudaGetSymbolAddress((void**)&W1, g_W1);
    cudaGetSymbolAddress((void**)&W2, g_W2);
    cudaGetSymbolAddress((void**)&H,  g_H);
    cudaGetSymbolAddress((void**)&A,  g_A);
    cudaGetSymbolAddress((void**)&dH, g_dH);
    cudaGetSymbolAddress((void**)&E,  g_E);
    cudaGetSymbolAddress((void**)&G1, g_G1);
    cudaGetSymbolAddress((void**)&G2, g_G2);
    cudaGetSymbolAddress((void**)&Hq, g_Hq);

    const dim3 thr(256);
    const float escale = 2.0f / (float)(ROWS_CHUNK * D_IN);  // 2/N for MSE grad

    // W <- mem_w, S <- 0
    init_kernel<<<WSZ / 256, thr>>>(mem_w1, mem_w2);

    // Q = x @ w_q   (row order);  K,V = x @ w_{k,v}  (chunk-major permuted store)
    {
        dim3 g(D_IN / 64, ROWS_TOTAL / 64);
        gemm64<false, false, 0><<<g, thr>>>(x, D_IN, w_q, D_IN, Q, D_IN, D_IN, nullptr, nullptr, 0.f);
        gemm64<false, false, 5><<<g, thr>>>(x, D_IN, w_k, D_IN, K, D_IN, D_IN, nullptr, nullptr, 0.f);
        gemm64<false, false, 5><<<g, thr>>>(x, D_IN, w_v, D_IN, V, D_IN, D_IN, nullptr, nullptr, 0.f);
    }

    // Sequential inner-loop memory updates (16 chunks)
    for (int c = 0; c < NCHUNK; c++) {
        const float* Kc = K + (size_t)c * ROWS_CHUNK * D_IN;
        const float* Vc = V + (size_t)c * ROWS_CHUNK * D_IN;

        // H = Kc @ W1 ; A = gelu(H)            [1024,1024] k=512
        {
            dim3 g(HID / 64, ROWS_CHUNK / 64);
            gemm64<false, false, 1><<<g, thr>>>(Kc, D_IN, W1, HID, H, HID, D_IN, nullptr, A, 0.f);
        }
        // E = (A @ W2 - Vc) * 2/N              [1024,512] k=1024
        {
            dim3 g(D_IN / 64, ROWS_CHUNK / 64);
            gemm64<false, false, 2><<<g, thr>>>(A, HID, W2, D_IN, E, D_IN, HID, Vc, nullptr, escale);
        }
        // G2 = A^T @ E                         [1024,512] k=1024  (transA)
        {
            dim3 g(D_IN / 64, HID / 64);
            gemm64<true, false, 0><<<g, thr>>>(A, HID, E, D_IN, G2, D_IN, ROWS_CHUNK, nullptr, nullptr, 0.f);
        }
        // dH = (E @ W2^T) * gelu'(H)           [1024,1024] k=512  (transB)
        {
            dim3 g(HID / 64, ROWS_CHUNK / 64);
            gemm64<false, true, 3><<<g, thr>>>(E, D_IN, W2, D_IN, dH, HID, D_IN, H, nullptr, 0.f);
        }
        // G1 = Kc^T @ dH                       [512,1024] k=1024  (transA)
        {
            dim3 g(HID / 64, D_IN / 64);
            gemm64<true, false, 0><<<g, thr>>>(Kc, D_IN, dH, HID, G1, HID, ROWS_CHUNK, nullptr, nullptr, 0.f);
        }
        // S = decay*S - lr*G ; W = (1-alpha)*W + S   (gated on update_mem)
        update_kernel<<<WSZ / 256, thr>>>(alpha_t, lr_t, decay_t, upd);
    }

    // Readout: Hq = gelu(Q @ W1) ; out = Hq @ W2
    {
        dim3 g1(HID / 64, ROWS_TOTAL / 64);
        gemm64<false, false, 4><<<g1, thr>>>(Q, D_IN, W1, HID, Hq, HID, D_IN, nullptr, nullptr, 0.f);
        dim3 g2(D_IN / 64, ROWS_TOTAL / 64);
        gemm64<false, false, 0><<<g2, thr>>>(Hq, HID, W2, D_IN, out, D_IN, HID, nullptr, nullptr, 0.f);
    }
    (void)in_sizes; (void)n_in; (void)out_size;
}

// round 3
// speedup vs baseline: 1.5997x; 1.5997x over previous
#include <cuda_runtime.h>
#include <cuda_fp16.h>
#include <cstdint>
#include <math.h>

// ---------------- problem constants ----------------------------------------
#define D_IN   512
#define HID    1024
#define SEQ    4096
#define BATCH  4
#define CHUNK  256
#define NCHUNK 16
#define ROWS_TOTAL (BATCH*SEQ)     // 16384
#define ROWS_CHUNK (BATCH*CHUNK)   // 1024
#define WSZ    (D_IN*HID)          // 524288

// ---------------- scratch (device globals; no allocation allowed) ----------
__device__ float g_Q [ROWS_TOTAL*D_IN];
__device__ float g_K [ROWS_TOTAL*D_IN];   // chunk-major: [c][b][t][d]
__device__ float g_V [ROWS_TOTAL*D_IN];
__device__ float g_W1[WSZ];
__device__ float g_W2[WSZ];
__device__ float g_S1[WSZ];
__device__ float g_S2[WSZ];
__device__ float g_H [ROWS_CHUNK*HID];
__device__ float g_A [ROWS_CHUNK*HID];
__device__ float g_dH[ROWS_CHUNK*HID];
__device__ float g_E [ROWS_CHUNK*D_IN];
__device__ float g_G1[WSZ];
__device__ float g_G2[WSZ];
__device__ float g_Hq[ROWS_TOTAL*HID];

// ---------------- math helpers ---------------------------------------------
__device__ __forceinline__ float gelu_f(float x) {
    return 0.5f * x * (1.0f + erff(x * 0.70710678118654752f));
}
__device__ __forceinline__ float gelu_grad_f(float x) {
    float cdf = 0.5f * (1.0f + erff(x * 0.70710678118654752f));
    float pdf = 0.3989422804014327f * __expf(-0.5f * x * x);
    return cdf + x * pdf;
}
__device__ __forceinline__ float sigmoid_f(float x) {
    return 1.0f / (1.0f + __expf(-x));
}

// ---------------- PTX helpers -----------------------------------------------
__device__ __forceinline__ uint32_t smem_u32(const void* p) {
    uint32_t a;
    asm("{ .reg .u64 t; cvta.to.shared.u64 t, %1; cvt.u32.u64 %0, t; }" : "=r"(a) : "l"(p));
    return a;
}
__device__ __forceinline__ void ldsm4(uint32_t a, uint32_t& r0, uint32_t& r1,
                                      uint32_t& r2, uint32_t& r3) {
    asm volatile("ldmatrix.sync.aligned.m8n8.x4.shared.b16 {%0,%1,%2,%3}, [%4];"
                 : "=r"(r0), "=r"(r1), "=r"(r2), "=r"(r3) : "r"(a));
}
__device__ __forceinline__ void ldsm4t(uint32_t a, uint32_t& r0, uint32_t& r1,
                                       uint32_t& r2, uint32_t& r3) {
    asm volatile("ldmatrix.sync.aligned.m8n8.x4.trans.shared.b16 {%0,%1,%2,%3}, [%4];"
                 : "=r"(r0), "=r"(r1), "=r"(r2), "=r"(r3) : "r"(a));
}
__device__ __forceinline__ void mma16816(float* c, const uint32_t* a, const uint32_t* b) {
    asm volatile(
        "mma.sync.aligned.m16n8k16.row.col.f32.f16.f16.f32 "
        "{%0,%1,%2,%3}, {%4,%5,%6,%7}, {%8,%9}, {%0,%1,%2,%3};"
        : "+f"(c[0]), "+f"(c[1]), "+f"(c[2]), "+f"(c[3])
        : "r"(a[0]), "r"(a[1]), "r"(a[2]), "r"(a[3]), "r"(b[0]), "r"(b[1]));
}
// split f32x4 -> hi fp16x4 (8B) + lo fp16x4 (8B)
__device__ __forceinline__ void cvt_split(float4 v, uint2& h, uint2& l) {
    __half2 h0 = __floats2half2_rn(v.x, v.y);
    __half2 h1 = __floats2half2_rn(v.z, v.w);
    float2 f0 = __half22float2(h0);
    float2 f1 = __half22float2(h1);
    __half2 l0 = __floats2half2_rn(v.x - f0.x, v.y - f0.y);
    __half2 l1 = __floats2half2_rn(v.z - f1.x, v.w - f1.y);
    h.x = *(uint32_t*)&h0;  h.y = *(uint32_t*)&h1;
    l.x = *(uint32_t*)&l0;  l.y = *(uint32_t*)&l1;
}

// SMEM per buffer: Ah[8K] Al[8K] Bh[8K] Bl[8K] = 32KB; double buffered = 64KB
#define TILE_BYTES 8192
#define BUF_BYTES  (4*TILE_BYTES)
#define SMEM_BYTES (2*BUF_BYTES)

// ---------------- fp16-split tensor-core GEMM -------------------------------
// C[M,N] = op(A) @ op(B); CTA tile 128x128, BK=32, 8 warps (4m x 2n), warp 32x64.
// TA=false: A[M,K] (lda=K-stride). TA=true: A[K,M] (lda=M-stride).
// TB=false: B[K,N] (ldb=N-stride). TB=true: B[N,K] (ldb=K-stride).
// EPI: 0 C=v | 1 C=v,out2=gelu(v) | 2 C=(v-aux)*scale | 3 C=v*gelu'(aux)
//      4 C=gelu(v) | 5 chunk-permuted store
template<bool TA, bool TB, int EPI>
__global__ void __launch_bounds__(256)
hgemm(const float* __restrict__ A, int lda,
      const float* __restrict__ B, int ldb,
      float* __restrict__ C, int ldc, int K,
      const float* __restrict__ aux, float* __restrict__ out2, float scale)
{
    extern __shared__ char smem[];
    const uint32_t sbase = smem_u32(smem);

    const int tid  = threadIdx.x;
    const int wid  = tid >> 5;
    const int lane = tid & 31;
    const int m0 = blockIdx.y * 128, n0 = blockIdx.x * 128;
    const int wm = (wid & 3) * 32;        // warp m-offset
    const int wn = (wid >> 2) * 64;       // warp n-offset

    float acc[2][8][4] = {};

    // ---- gmem staging setup (4 float4 per thread per operand) ----
    const float* pA[4];
    const float* pB[4];
    uint32_t aoff[4], boff[4];
    long strideA, strideB;
    #pragma unroll
    for (int i = 0; i < 4; i++) {
        int fi = tid + i * 256;
        if (!TA) {  // RK layout: rows=m (64B rows of 32 fp16)
            int r = fi >> 3, kq = fi & 7;
            pA[i] = A + (size_t)(m0 + r) * lda + kq * 4;
            int g = kq >> 1, hf = kq & 1;
            aoff[i] = r * 64 + ((g ^ ((r >> 1) & 3)) << 4) + hf * 8;
        } else {    // KR layout: rows=k (256B rows of 128 fp16)
            int kr = fi >> 5, rq = fi & 31;
            pA[i] = A + (size_t)kr * lda + m0 + rq * 4;
            aoff[i] = kr * 256 + (((rq >> 1) ^ (kr & 7)) << 4) + (rq & 1) * 8;
        }
        if (TB) {   // RN layout (rows=n, 64B rows)
            int r = fi >> 3, kq = fi & 7;
            pB[i] = B + (size_t)(n0 + r) * ldb + kq * 4;
            int g = kq >> 1, hf = kq & 1;
            boff[i] = r * 64 + ((g ^ ((r >> 1) & 3)) << 4) + hf * 8;
        } else {    // KN layout (rows=k, 256B rows)
            int kr = fi >> 5, rq = fi & 31;
            pB[i] = B + (size_t)kr * ldb + n0 + rq * 4;
            boff[i] = kr * 256 + (((rq >> 1) ^ (kr & 7)) << 4) + (rq & 1) * 8;
        }
    }
    strideA = TA ? (long)32 * lda : 32;
    strideB = TB ? 32 : (long)32 * ldb;

    // ---- ldmatrix address precompute (constant across chunks; add buf base) --
    uint32_t aA[2][2], aB[2][4];
    #pragma unroll
    for (int s = 0; s < 2; s++) {
        #pragma unroll
        for (int mt = 0; mt < 2; mt++) {
            if (!TA) {
                int r = wm + mt * 16 + (lane & 15);
                int g = 2 * s + (lane >> 4);
                aA[s][mt] = r * 64 + ((g ^ ((r >> 1) & 3)) << 4);
            } else {
                int k = 16 * s + (lane & 7) + (lane >> 4) * 8;
                int mg = ((wm + mt * 16) >> 3) + ((lane >> 3) & 1);
                aA[s][mt] = k * 256 + ((mg ^ (k & 7)) << 4);
            }
        }
        #pragma unroll
        for (int j = 0; j < 4; j++) {
            if (!TB) {  // KN + trans ldmatrix
                int k = 16 * s + (lane & 7) + ((lane >> 3) & 1) * 8;
                int ng = ((wn + j * 16) >> 3) + (lane >> 4);
                aB[s][j] = k * 256 + ((ng ^ (k & 7)) << 4);
            } else {    // RN + non-trans ldmatrix
                int n = wn + j * 16 + (lane & 7) + (lane >> 4) * 8;
                int g = 2 * s + ((lane >> 3) & 1);
                aB[s][j] = n * 64 + ((g ^ ((n >> 1) & 3)) << 4);
            }
        }
    }

    const int NC = K >> 5;
    float4 sa[4], sb[4];

    // prologue: stage + store chunk 0
    #pragma unroll
    for (int i = 0; i < 4; i++) { sa[i] = *(const float4*)pA[i]; sb[i] = *(const float4*)pB[i]; }
    {
        uint32_t b0 = 0;
        #pragma unroll
        for (int i = 0; i < 4; i++) {
            uint2 h, l;
            cvt_split(sa[i], h, l);
            *(uint2*)(smem + b0 + aoff[i])              = h;
            *(uint2*)(smem + b0 + TILE_BYTES + aoff[i]) = l;
            cvt_split(sb[i], h, l);
            *(uint2*)(smem + b0 + 2*TILE_BYTES + boff[i]) = h;
            *(uint2*)(smem + b0 + 3*TILE_BYTES + boff[i]) = l;
        }
    }
    __syncthreads();

    for (int c = 0; c < NC; c++) {
        const int buf = c & 1;
        // stage next chunk
        if (c + 1 < NC) {
            #pragma unroll
            for (int i = 0; i < 4; i++) {
                sa[i] = *(const float4*)(pA[i] + (c + 1) * strideA);
                sb[i] = *(const float4*)(pB[i] + (c + 1) * strideB);
            }
        }
        // compute from current buffer
        const uint32_t tAh = sbase + buf * BUF_BYTES;
        const uint32_t tAl = tAh + TILE_BYTES;
        const uint32_t tBh = tAh + 2 * TILE_BYTES;
        const uint32_t tBl = tAh + 3 * TILE_BYTES;
        #pragma unroll
        for (int s = 0; s < 2; s++) {
            uint32_t fAh[2][4], fAl[2][4], fBh[8][2], fBl[8][2];
            #pragma unroll
            for (int mt = 0; mt < 2; mt++) {
                if (!TA) {
                    ldsm4 (tAh + aA[s][mt], fAh[mt][0], fAh[mt][1], fAh[mt][2], fAh[mt][3]);
                    ldsm4 (tAl + aA[s][mt], fAl[mt][0], fAl[mt][1], fAl[mt][2], fAl[mt][3]);
                } else {
                    ldsm4t(tAh + aA[s][mt], fAh[mt][0], fAh[mt][1], fAh[mt][2], fAh[mt][3]);
                    ldsm4t(tAl + aA[s][mt], fAl[mt][0], fAl[mt][1], fAl[mt][2], fAl[mt][3]);
                }
            }
            #pragma unroll
            for (int j = 0; j < 4; j++) {
                if (!TB) {
                    ldsm4t(tBh + aB[s][j], fBh[2*j][0], fBh[2*j][1], fBh[2*j+1][0], fBh[2*j+1][1]);
                    ldsm4t(tBl + aB[s][j], fBl[2*j][0], fBl[2*j][1], fBl[2*j+1][0], fBl[2*j+1][1]);
                } else {
                    ldsm4 (tBh + aB[s][j], fBh[2*j][0], fBh[2*j][1], fBh[2*j+1][0], fBh[2*j+1][1]);
                    ldsm4 (tBl + aB[s][j], fBl[2*j][0], fBl[2*j][1], fBl[2*j+1][0], fBl[2*j+1][1]);
                }
            }
            #pragma unroll
            for (int mt = 0; mt < 2; mt++)
                #pragma unroll
                for (int nt = 0; nt < 8; nt++) {
                    mma16816(acc[mt][nt], fAh[mt], fBh[nt]);   // hi*hi
                    mma16816(acc[mt][nt], fAh[mt], fBl[nt]);   // hi*lo
                    mma16816(acc[mt][nt], fAl[mt], fBh[nt]);   // lo*hi
                }
        }
        // store next chunk into other buffer
        if (c + 1 < NC) {
            uint32_t b1 = (buf ^ 1) * BUF_BYTES;
            #pragma unroll
            for (int i = 0; i < 4; i++) {
                uint2 h, l;
                cvt_split(sa[i], h, l);
                *(uint2*)(smem + b1 + aoff[i])              = h;
                *(uint2*)(smem + b1 + TILE_BYTES + aoff[i]) = l;
                cvt_split(sb[i], h, l);
                *(uint2*)(smem + b1 + 2*TILE_BYTES + boff[i]) = h;
                *(uint2*)(smem + b1 + 3*TILE_BYTES + boff[i]) = l;
            }
        }
        __syncthreads();
    }

    // ---- epilogue ----
    #pragma unroll
    for (int mt = 0; mt < 2; mt++) {
        #pragma unroll
        for (int half = 0; half < 2; half++) {
            int r = m0 + wm + mt * 16 + (lane >> 2) + half * 8;
            #pragma unroll
            for (int nt = 0; nt < 8; nt++) {
                int cc = n0 + wn + nt * 8 + 2 * (lane & 3);
                float v0 = acc[mt][nt][half * 2 + 0];
                float v1 = acc[mt][nt][half * 2 + 1];
                size_t idx = (size_t)r * ldc + cc;
                if (EPI == 0) {
                    *(float2*)(C + idx) = make_float2(v0, v1);
                } else if (EPI == 1) {
                    *(float2*)(C + idx) = make_float2(v0, v1);
                    *(float2*)(out2 + idx) = make_float2(gelu_f(v0), gelu_f(v1));
                } else if (EPI == 2) {
                    float2 a2 = *(const float2*)(aux + idx);
                    *(float2*)(C + idx) = make_float2((v0 - a2.x) * scale, (v1 - a2.y) * scale);
                } else if (EPI == 3) {
                    float2 a2 = *(const float2*)(aux + idx);
                    *(float2*)(C + idx) = make_float2(v0 * gelu_grad_f(a2.x), v1 * gelu_grad_f(a2.y));
                } else if (EPI == 4) {
                    *(float2*)(C + idx) = make_float2(gelu_f(v0), gelu_f(v1));
                } else {  // EPI == 5: chunk-permuted store
                    int b = r >> 12, s = r & 4095, ch = s >> 8, t = s & 255;
                    int orow = ch * 1024 + b * 256 + t;
                    *(float2*)(C + (size_t)orow * ldc + cc) = make_float2(v0, v1);
                }
            }
        }
    }
}

// ---------------- init: W <- mem_w, S <- 0 ----------------------------------
__global__ void init_kernel(const float* __restrict__ w1, const float* __restrict__ w2) {
    int i = blockIdx.x * 256 + threadIdx.x;
    if (i < WSZ) {
        g_W1[i] = w1[i];
        g_W2[i] = w2[i];
        g_S1[i] = 0.0f;
        g_S2[i] = 0.0f;
    }
}

// ---------------- momentum + weight-decay update -----------------------------
__global__ void update_kernel(const float* __restrict__ alpha_t,
                              const float* __restrict__ lr_t,
                              const float* __restrict__ decay_t,
                              const int*  __restrict__ update_mem) {
    if (*update_mem == 0) return;
    int i = blockIdx.x * 256 + threadIdx.x;
    if (i >= WSZ) return;
    float alpha = sigmoid_f(*alpha_t);
    float lr    = sigmoid_f(*lr_t);
    float decay = sigmoid_f(*decay_t);
    float om = 1.0f - alpha;

    float s1 = decay * g_S1[i] - lr * g_G1[i];
    g_S1[i] = s1;
    g_W1[i] = om * g_W1[i] + s1;

    float s2 = decay * g_S2[i] - lr * g_G2[i];
    g_S2[i] = s2;
    g_W2[i] = om * g_W2[i] + s2;
}

// ---------------- launcher ---------------------------------------------------
extern "C" void kernel_launch(void* const* d_in, const int* in_sizes, int n_in,
                              void* d_out, int out_size)
{
    const float* x       = (const float*)d_in[0];
    const float* w_q     = (const float*)d_in[1];
    const float* w_k     = (const float*)d_in[2];
    const float* w_v     = (const float*)d_in[3];
    const float* mem_w1  = (const float*)d_in[4];
    const float* mem_w2  = (const float*)d_in[5];
    const float* alpha_t = (const float*)d_in[6];
    const float* lr_t    = (const float*)d_in[7];
    const float* decay_t = (const float*)d_in[8];
    const int*   upd     = (const int*)d_in[9];
    float* out = (float*)d_out;

    float *Q, *K, *V, *W1, *W2, *H, *A, *dH, *E, *G1, *G2, *Hq;
    cudaGetSymbolAddress((void**)&Q,  g_Q);
    cudaGetSymbolAddress((void**)&K,  g_K);
    cudaGetSymbolAddress((void**)&V,  g_V);
    cudaGetSymbolAddress((void**)&W1, g_W1);
    cudaGetSymbolAddress((void**)&W2, g_W2);
    cudaGetSymbolAddress((void**)&H,  g_H);
    cudaGetSymbolAddress((void**)&A,  g_A);
    cudaGetSymbolAddress((void**)&dH, g_dH);
    cudaGetSymbolAddress((void**)&E,  g_E);
    cudaGetSymbolAddress((void**)&G1, g_G1);
    cudaGetSymbolAddress((void**)&G2, g_G2);
    cudaGetSymbolAddress((void**)&Hq, g_Hq);

    cudaFuncSetAttribute(hgemm<false,false,0>, cudaFuncAttributeMaxDynamicSharedMemorySize, SMEM_BYTES);
    cudaFuncSetAttribute(hgemm<false,false,1>, cudaFuncAttributeMaxDynamicSharedMemorySize, SMEM_BYTES);
    cudaFuncSetAttribute(hgemm<false,false,2>, cudaFuncAttributeMaxDynamicSharedMemorySize, SMEM_BYTES);
    cudaFuncSetAttribute(hgemm<false,false,4>, cudaFuncAttributeMaxDynamicSharedMemorySize, SMEM_BYTES);
    cudaFuncSetAttribute(hgemm<false,false,5>, cudaFuncAttributeMaxDynamicSharedMemorySize, SMEM_BYTES);
    cudaFuncSetAttribute(hgemm<true ,false,0>, cudaFuncAttributeMaxDynamicSharedMemorySize, SMEM_BYTES);
    cudaFuncSetAttribute(hgemm<false,true ,3>, cudaFuncAttributeMaxDynamicSharedMemorySize, SMEM_BYTES);

    const dim3 thr(256);
    const float escale = 2.0f / (float)(ROWS_CHUNK * D_IN);

    init_kernel<<<WSZ / 256, thr>>>(mem_w1, mem_w2);

    // Q = x @ w_q ; K,V = x @ w_{k,v} (chunk-major permuted store)
    {
        dim3 g(D_IN / 128, ROWS_TOTAL / 128);
        hgemm<false,false,0><<<g, thr, SMEM_BYTES>>>(x, D_IN, w_q, D_IN, Q, D_IN, D_IN, nullptr, nullptr, 0.f);
        hgemm<false,false,5><<<g, thr, SMEM_BYTES>>>(x, D_IN, w_k, D_IN, K, D_IN, D_IN, nullptr, nullptr, 0.f);
        hgemm<false,false,5><<<g, thr, SMEM_BYTES>>>(x, D_IN, w_v, D_IN, V, D_IN, D_IN, nullptr, nullptr, 0.f);
    }

    for (int c = 0; c < NCHUNK; c++) {
        const float* Kc = K + (size_t)c * ROWS_CHUNK * D_IN;
        const float* Vc = V + (size_t)c * ROWS_CHUNK * D_IN;

        // H = Kc @ W1 ; A = gelu(H)           [1024,1024] k=512
        {
            dim3 g(HID / 128, ROWS_CHUNK / 128);
            hgemm<false,false,1><<<g, thr, SMEM_BYTES>>>(Kc, D_IN, W1, HID, H, HID, D_IN, nullptr, A, 0.f);
        }
        // E = (A @ W2 - Vc) * 2/N             [1024,512] k=1024
        {
            dim3 g(D_IN / 128, ROWS_CHUNK / 128);
            hgemm<false,false,2><<<g, thr, SMEM_BYTES>>>(A, HID, W2, D_IN, E, D_IN, HID, Vc, nullptr, escale);
        }
        // G2 = A^T @ E                        [1024,512] k=1024
        {
            dim3 g(D_IN / 128, HID / 128);
            hgemm<true,false,0><<<g, thr, SMEM_BYTES>>>(A, HID, E, D_IN, G2, D_IN, ROWS_CHUNK, nullptr, nullptr, 0.f);
        }
        // dH = (E @ W2^T) * gelu'(H)          [1024,1024] k=512
        {
            dim3 g(HID / 128, ROWS_CHUNK / 128);
            hgemm<false,true,3><<<g, thr, SMEM_BYTES>>>(E, D_IN, W2, D_IN, dH, HID, D_IN, H, nullptr, 0.f);
        }
        // G1 = Kc^T @ dH                      [512,1024] k=1024
        {
            dim3 g(HID / 128, D_IN / 128);
            hgemm<true,false,0><<<g, thr, SMEM_BYTES>>>(Kc, D_IN, dH, HID, G1, HID, ROWS_CHUNK, nullptr, nullptr, 0.f);
        }
        update_kernel<<<WSZ / 256, thr>>>(alpha_t, lr_t, decay_t, upd);
    }

    // Readout: Hq = gelu(Q @ W1) ; out = Hq @ W2
    {
        dim3 g1(HID / 128, ROWS_TOTAL / 128);
        hgemm<false,false,4><<<g1, thr, SMEM_BYTES>>>(Q, D_IN, W1, HID, Hq, HID, D_IN, nullptr, nullptr, 0.f);
        dim3 g2(D_IN / 128, ROWS_TOTAL / 128);
        hgemm<false,false,0><<<g2, thr, SMEM_BYTES>>>(Hq, HID, W2, D_IN, out, D_IN, HID, nullptr, nullptr, 0.f);
    }
    (void)in_sizes; (void)n_in; (void)out_size;
}

// round 4
// speedup vs baseline: 2.6443x; 1.6530x over previous
#include <cuda_runtime.h>
#include <cuda_fp16.h>
#include <cstdint>
#include <math.h>

// ---------------- problem constants ----------------------------------------
#define D_IN   512
#define HID    1024
#define SEQ    4096
#define BATCH  4
#define CHUNK  256
#define NCHUNK 16
#define ROWS_TOTAL (BATCH*SEQ)     // 16384
#define ROWS_CHUNK (BATCH*CHUNK)   // 1024
#define WSZ    (D_IN*HID)          // 524288
#define NB     148                 // persistent grid size (<= SM count)

// ---------------- scratch (device globals; no allocation allowed) ----------
__device__ float g_Q [ROWS_TOTAL*D_IN];
__device__ float g_K [ROWS_TOTAL*D_IN];   // chunk-major: [c][b][t][d]
__device__ float g_V [ROWS_TOTAL*D_IN];
__device__ float g_W1[WSZ];
__device__ float g_W2[WSZ];
__device__ float g_S1[WSZ];
__device__ float g_S2[WSZ];
__device__ float g_H [ROWS_CHUNK*HID];
__device__ float g_A [ROWS_CHUNK*HID];
__device__ float g_dH[ROWS_CHUNK*HID];
__device__ float g_E [ROWS_CHUNK*D_IN];
__device__ float g_G2[WSZ];
__device__ float g_Hq[ROWS_TOTAL*HID];
__device__ unsigned g_arrive;

// ---------------- math helpers ---------------------------------------------
__device__ __forceinline__ float gelu_f(float x) {
    return 0.5f * x * (1.0f + erff(x * 0.70710678118654752f));
}
__device__ __forceinline__ float gelu_grad_f(float x) {
    float cdf = 0.5f * (1.0f + erff(x * 0.70710678118654752f));
    float pdf = 0.3989422804014327f * __expf(-0.5f * x * x);
    return cdf + x * pdf;
}
__device__ __forceinline__ float sigmoid_f(float x) {
    return 1.0f / (1.0f + __expf(-x));
}

// ---------------- PTX helpers -----------------------------------------------
__device__ __forceinline__ uint32_t smem_u32(const void* p) {
    uint32_t a;
    asm("{ .reg .u64 t; cvta.to.shared.u64 t, %1; cvt.u32.u64 %0, t; }" : "=r"(a) : "l"(p));
    return a;
}
__device__ __forceinline__ void ldsm4(uint32_t a, uint32_t& r0, uint32_t& r1,
                                      uint32_t& r2, uint32_t& r3) {
    asm volatile("ldmatrix.sync.aligned.m8n8.x4.shared.b16 {%0,%1,%2,%3}, [%4];"
                 : "=r"(r0), "=r"(r1), "=r"(r2), "=r"(r3) : "r"(a));
}
__device__ __forceinline__ void ldsm4t(uint32_t a, uint32_t& r0, uint32_t& r1,
                                       uint32_t& r2, uint32_t& r3) {
    asm volatile("ldmatrix.sync.aligned.m8n8.x4.trans.shared.b16 {%0,%1,%2,%3}, [%4];"
                 : "=r"(r0), "=r"(r1), "=r"(r2), "=r"(r3) : "r"(a));
}
__device__ __forceinline__ void mma16816(float* c, const uint32_t* a, const uint32_t* b) {
    asm volatile(
        "mma.sync.aligned.m16n8k16.row.col.f32.f16.f16.f32 "
        "{%0,%1,%2,%3}, {%4,%5,%6,%7}, {%8,%9}, {%0,%1,%2,%3};"
        : "+f"(c[0]), "+f"(c[1]), "+f"(c[2]), "+f"(c[3])
        : "r"(a[0]), "r"(a[1]), "r"(a[2]), "r"(a[3]), "r"(b[0]), "r"(b[1]));
}
__device__ __forceinline__ void cvt_split(float4 v, uint2& h, uint2& l) {
    __half2 h0 = __floats2half2_rn(v.x, v.y);
    __half2 h1 = __floats2half2_rn(v.z, v.w);
    float2 f0 = __half22float2(h0);
    float2 f1 = __half22float2(h1);
    __half2 l0 = __floats2half2_rn(v.x - f0.x, v.y - f0.y);
    __half2 l1 = __floats2half2_rn(v.z - f1.x, v.w - f1.y);
    h.x = *(uint32_t*)&h0;  h.y = *(uint32_t*)&h1;
    l.x = *(uint32_t*)&l0;  l.y = *(uint32_t*)&l1;
}

// ============================================================================
// Standalone 128x128 hgemm (QKV + readout) — unchanged from round 3
// ============================================================================
#define TILE_BYTES 8192
#define BUF_BYTES  (4*TILE_BYTES)
#define SMEM_BYTES (2*BUF_BYTES)

template<bool TA, bool TB, int EPI>
__global__ void __launch_bounds__(256)
hgemm(const float* __restrict__ A, int lda,
      const float* __restrict__ B, int ldb,
      float* __restrict__ C, int ldc, int K,
      const float* __restrict__ aux, float* __restrict__ out2, float scale)
{
    extern __shared__ char smem[];
    const uint32_t sbase = smem_u32(smem);

    const int tid  = threadIdx.x;
    const int wid  = tid >> 5;
    const int lane = tid & 31;
    const int m0 = blockIdx.y * 128, n0 = blockIdx.x * 128;
    const int wm = (wid & 3) * 32;
    const int wn = (wid >> 2) * 64;

    float acc[2][8][4] = {};

    const float* pA[4];
    const float* pB[4];
    uint32_t aoff[4], boff[4];
    long strideA, strideB;
    #pragma unroll
    for (int i = 0; i < 4; i++) {
        int fi = tid + i * 256;
        if (!TA) {
            int r = fi >> 3, kq = fi & 7;
            pA[i] = A + (size_t)(m0 + r) * lda + kq * 4;
            int g = kq >> 1, hf = kq & 1;
            aoff[i] = r * 64 + ((g ^ ((r >> 1) & 3)) << 4) + hf * 8;
        } else {
            int kr = fi >> 5, rq = fi & 31;
            pA[i] = A + (size_t)kr * lda + m0 + rq * 4;
            aoff[i] = kr * 256 + (((rq >> 1) ^ (kr & 7)) << 4) + (rq & 1) * 8;
        }
        if (TB) {
            int r = fi >> 3, kq = fi & 7;
            pB[i] = B + (size_t)(n0 + r) * ldb + kq * 4;
            int g = kq >> 1, hf = kq & 1;
            boff[i] = r * 64 + ((g ^ ((r >> 1) & 3)) << 4) + hf * 8;
        } else {
            int kr = fi >> 5, rq = fi & 31;
            pB[i] = B + (size_t)kr * ldb + n0 + rq * 4;
            boff[i] = kr * 256 + (((rq >> 1) ^ (kr & 7)) << 4) + (rq & 1) * 8;
        }
    }
    strideA = TA ? (long)32 * lda : 32;
    strideB = TB ? 32 : (long)32 * ldb;

    uint32_t aA[2][2], aB[2][4];
    #pragma unroll
    for (int s = 0; s < 2; s++) {
        #pragma unroll
        for (int mt = 0; mt < 2; mt++) {
            if (!TA) {
                int r = wm + mt * 16 + (lane & 15);
                int g = 2 * s + (lane >> 4);
                aA[s][mt] = r * 64 + ((g ^ ((r >> 1) & 3)) << 4);
            } else {
                int k = 16 * s + (lane & 7) + (lane >> 4) * 8;
                int mg = ((wm + mt * 16) >> 3) + ((lane >> 3) & 1);
                aA[s][mt] = k * 256 + ((mg ^ (k & 7)) << 4);
            }
        }
        #pragma unroll
        for (int j = 0; j < 4; j++) {
            if (!TB) {
                int k = 16 * s + (lane & 7) + ((lane >> 3) & 1) * 8;
                int ng = ((wn + j * 16) >> 3) + (lane >> 4);
                aB[s][j] = k * 256 + ((ng ^ (k & 7)) << 4);
            } else {
                int n = wn + j * 16 + (lane & 7) + (lane >> 4) * 8;
                int g = 2 * s + ((lane >> 3) & 1);
                aB[s][j] = n * 64 + ((g ^ ((n >> 1) & 3)) << 4);
            }
        }
    }

    const int NC = K >> 5;
    float4 sa[4], sb[4];

    #pragma unroll
    for (int i = 0; i < 4; i++) { sa[i] = *(const float4*)pA[i]; sb[i] = *(const float4*)pB[i]; }
    {
        #pragma unroll
        for (int i = 0; i < 4; i++) {
            uint2 h, l;
            cvt_split(sa[i], h, l);
            *(uint2*)(smem + aoff[i])              = h;
            *(uint2*)(smem + TILE_BYTES + aoff[i]) = l;
            cvt_split(sb[i], h, l);
            *(uint2*)(smem + 2*TILE_BYTES + boff[i]) = h;
            *(uint2*)(smem + 3*TILE_BYTES + boff[i]) = l;
        }
    }
    __syncthreads();

    for (int c = 0; c < NC; c++) {
        const int buf = c & 1;
        if (c + 1 < NC) {
            #pragma unroll
            for (int i = 0; i < 4; i++) {
                sa[i] = *(const float4*)(pA[i] + (c + 1) * strideA);
                sb[i] = *(const float4*)(pB[i] + (c + 1) * strideB);
            }
        }
        const uint32_t tAh = sbase + buf * BUF_BYTES;
        const uint32_t tAl = tAh + TILE_BYTES;
        const uint32_t tBh = tAh + 2 * TILE_BYTES;
        const uint32_t tBl = tAh + 3 * TILE_BYTES;
        #pragma unroll
        for (int s = 0; s < 2; s++) {
            uint32_t fAh[2][4], fAl[2][4], fBh[8][2], fBl[8][2];
            #pragma unroll
            for (int mt = 0; mt < 2; mt++) {
                if (!TA) {
                    ldsm4 (tAh + aA[s][mt], fAh[mt][0], fAh[mt][1], fAh[mt][2], fAh[mt][3]);
                    ldsm4 (tAl + aA[s][mt], fAl[mt][0], fAl[mt][1], fAl[mt][2], fAl[mt][3]);
                } else {
                    ldsm4t(tAh + aA[s][mt], fAh[mt][0], fAh[mt][1], fAh[mt][2], fAh[mt][3]);
                    ldsm4t(tAl + aA[s][mt], fAl[mt][0], fAl[mt][1], fAl[mt][2], fAl[mt][3]);
                }
            }
            #pragma unroll
            for (int j = 0; j < 4; j++) {
                if (!TB) {
                    ldsm4t(tBh + aB[s][j], fBh[2*j][0], fBh[2*j][1], fBh[2*j+1][0], fBh[2*j+1][1]);
                    ldsm4t(tBl + aB[s][j], fBl[2*j][0], fBl[2*j][1], fBl[2*j+1][0], fBl[2*j+1][1]);
                } else {
                    ldsm4 (tBh + aB[s][j], fBh[2*j][0], fBh[2*j][1], fBh[2*j+1][0], fBh[2*j+1][1]);
                    ldsm4 (tBl + aB[s][j], fBl[2*j][0], fBl[2*j][1], fBl[2*j+1][0], fBl[2*j+1][1]);
                }
            }
            #pragma unroll
            for (int mt = 0; mt < 2; mt++)
                #pragma unroll
                for (int nt = 0; nt < 8; nt++) {
                    mma16816(acc[mt][nt], fAh[mt], fBh[nt]);
                    mma16816(acc[mt][nt], fAh[mt], fBl[nt]);
                    mma16816(acc[mt][nt], fAl[mt], fBh[nt]);
                }
        }
        if (c + 1 < NC) {
            uint32_t b1 = (buf ^ 1) * BUF_BYTES;
            #pragma unroll
            for (int i = 0; i < 4; i++) {
                uint2 h, l;
                cvt_split(sa[i], h, l);
                *(uint2*)(smem + b1 + aoff[i])              = h;
                *(uint2*)(smem + b1 + TILE_BYTES + aoff[i]) = l;
                cvt_split(sb[i], h, l);
                *(uint2*)(smem + b1 + 2*TILE_BYTES + boff[i]) = h;
                *(uint2*)(smem + b1 + 3*TILE_BYTES + boff[i]) = l;
            }
        }
        __syncthreads();
    }

    #pragma unroll
    for (int mt = 0; mt < 2; mt++) {
        #pragma unroll
        for (int half = 0; half < 2; half++) {
            int r = m0 + wm + mt * 16 + (lane >> 2) + half * 8;
            #pragma unroll
            for (int nt = 0; nt < 8; nt++) {
                int cc = n0 + wn + nt * 8 + 2 * (lane & 3);
                float v0 = acc[mt][nt][half * 2 + 0];
                float v1 = acc[mt][nt][half * 2 + 1];
                size_t idx = (size_t)r * ldc + cc;
                if (EPI == 0) {
                    *(float2*)(C + idx) = make_float2(v0, v1);
                } else if (EPI == 4) {
                    *(float2*)(C + idx) = make_float2(gelu_f(v0), gelu_f(v1));
                } else {  // EPI == 5: chunk-permuted store
                    int b = r >> 12, s = r & 4095, ch = s >> 8, t = s & 255;
                    int orow = ch * 1024 + b * 256 + t;
                    *(float2*)(C + (size_t)orow * ldc + cc) = make_float2(v0, v1);
                }
            }
        }
    }
}

// ============================================================================
// Persistent chunk-loop kernel: device-side tile GEMM (BN=128, BK=32, 8 warps)
// warps: 2(m) x 4(n); warp tile (BM/2) x 32.
// EPI: 0 C=v | 1 C=v,out2=gelu | 2 C=(v-aux)*scale | 3 C=v*gelu'(aux)
//      6 fused W1/S1 momentum update (C=W1, S=S1)
// ============================================================================
#define P_SMEM 49152   // max: BM=64 double buffer = 2*(2*4096 + 2*8192)

template<int BM, bool TA, bool TB, int EPI>
__device__ __forceinline__ void tile_gemm(
    const float* __restrict__ A, int lda,
    const float* __restrict__ B, int ldb,
    float* __restrict__ C, int ldc, int K,
    const float* __restrict__ aux, float* __restrict__ out2, float scale,
    int m0, int n0, char* smem, uint32_t sbase,
    float decay, float lr, float om, float* __restrict__ S)
{
    constexpr int AI  = BM / 32;        // A float4 per thread per chunk
    constexpr int A_T = BM * 64;        // one A tile (hi or lo) bytes
    constexpr int B_T = 8192;
    constexpr int BUF = 2 * A_T + 2 * B_T;
    constexpr int MT  = BM / 32;        // m16 frags per warp

    const int tid = threadIdx.x, wid = tid >> 5, lane = tid & 31;
    const int wm = (wid & 1) * (BM / 2);
    const int wn = (wid >> 1) * 32;

    float acc[MT][4][4];
    #pragma unroll
    for (int a = 0; a < MT; a++)
        #pragma unroll
        for (int b = 0; b < 4; b++)
            #pragma unroll
            for (int d = 0; d < 4; d++) acc[a][b][d] = 0.f;

    const float* pA[AI]; uint32_t aoff[AI];
    const float* pB[4];  uint32_t boff[4];
    #pragma unroll
    for (int i = 0; i < AI; i++) {
        int fi = tid + i * 256;
        if (!TA) {
            int r = fi >> 3, kq = fi & 7;
            pA[i] = A + (size_t)(m0 + r) * lda + kq * 4;
            aoff[i] = r * 64 + (((kq >> 1) ^ ((r >> 1) & 3)) << 4) + (kq & 1) * 8;
        } else {
            constexpr int RQ = BM / 4;
            int kr = fi / RQ, rq = fi % RQ;
            pA[i] = A + (size_t)kr * lda + m0 + rq * 4;
            if (BM == 64)
                aoff[i] = kr * 128 + (((rq >> 1) ^ (kr & 7)) << 4) + (rq & 1) * 8;
            else
                aoff[i] = kr * 64  + (((rq >> 1) ^ (kr & 3)) << 4) + (rq & 1) * 8;
        }
    }
    #pragma unroll
    for (int i = 0; i < 4; i++) {
        int fi = tid + i * 256;
        if (TB) {
            int r = fi >> 3, kq = fi & 7;
            pB[i] = B + (size_t)(n0 + r) * ldb + kq * 4;
            boff[i] = r * 64 + (((kq >> 1) ^ ((r >> 1) & 3)) << 4) + (kq & 1) * 8;
        } else {
            int kr = fi >> 5, rq = fi & 31;
            pB[i] = B + (size_t)kr * ldb + n0 + rq * 4;
            boff[i] = kr * 256 + (((rq >> 1) ^ (kr & 7)) << 4) + (rq & 1) * 8;
        }
    }
    const long strideA = TA ? (long)32 * lda : 32;
    const long strideB = TB ? 32 : (long)32 * ldb;

    uint32_t aA[2][MT], aB[2][2];
    #pragma unroll
    for (int s = 0; s < 2; s++) {
        #pragma unroll
        for (int mt = 0; mt < MT; mt++) {
            if (!TA) {
                int r = wm + mt * 16 + (lane & 15);
                int g = 2 * s + (lane >> 4);
                aA[s][mt] = r * 64 + ((g ^ ((r >> 1) & 3)) << 4);
            } else {
                int k = 16 * s + (lane & 7) + (lane >> 4) * 8;
                int mg = ((wm + mt * 16) >> 3) + ((lane >> 3) & 1);
                aA[s][mt] = (BM == 64) ? k * 128 + ((mg ^ (k & 7)) << 4)
                                       : k * 64  + ((mg ^ (k & 3)) << 4);
            }
        }
        #pragma unroll
        for (int j = 0; j < 2; j++) {
            if (!TB) {
                int k = 16 * s + (lane & 7) + ((lane >> 3) & 1) * 8;
                int ng = ((wn + j * 16) >> 3) + (lane >> 4);
                aB[s][j] = k * 256 + ((ng ^ (k & 7)) << 4);
            } else {
                int n = wn + j * 16 + (lane & 7) + (lane >> 4) * 8;
                int g = 2 * s + ((lane >> 3) & 1);
                aB[s][j] = n * 64 + ((g ^ ((n >> 1) & 3)) << 4);
            }
        }
    }

    const int NC = K >> 5;
    float4 sa[AI], sb[4];

    #pragma unroll
    for (int i = 0; i < AI; i++) sa[i] = *(const float4*)pA[i];
    #pragma unroll
    for (int i = 0; i < 4;  i++) sb[i] = *(const float4*)pB[i];
    {
        #pragma unroll
        for (int i = 0; i < AI; i++) {
            uint2 h, l; cvt_split(sa[i], h, l);
            *(uint2*)(smem + aoff[i])       = h;
            *(uint2*)(smem + A_T + aoff[i]) = l;
        }
        #pragma unroll
        for (int i = 0; i < 4; i++) {
            uint2 h, l; cvt_split(sb[i], h, l);
            *(uint2*)(smem + 2*A_T + boff[i])       = h;
            *(uint2*)(smem + 2*A_T + B_T + boff[i]) = l;
        }
    }
    __syncthreads();

    for (int c = 0; c < NC; c++) {
        const int buf = c & 1;
        if (c + 1 < NC) {
            #pragma unroll
            for (int i = 0; i < AI; i++) sa[i] = *(const float4*)(pA[i] + (c + 1) * strideA);
            #pragma unroll
            for (int i = 0; i < 4;  i++) sb[i] = *(const float4*)(pB[i] + (c + 1) * strideB);
        }
        const uint32_t tAh = sbase + buf * BUF;
        const uint32_t tAl = tAh + A_T;
        const uint32_t tBh = tAh + 2 * A_T;
        const uint32_t tBl = tBh + B_T;
        #pragma unroll
        for (int s = 0; s < 2; s++) {
            uint32_t fAh[MT][4], fAl[MT][4], fBh[4][2], fBl[4][2];
            #pragma unroll
            for (int mt = 0; mt < MT; mt++) {
                if (!TA) {
                    ldsm4 (tAh + aA[s][mt], fAh[mt][0], fAh[mt][1], fAh[mt][2], fAh[mt][3]);
                    ldsm4 (tAl + aA[s][mt], fAl[mt][0], fAl[mt][1], fAl[mt][2], fAl[mt][3]);
                } else {
                    ldsm4t(tAh + aA[s][mt], fAh[mt][0], fAh[mt][1], fAh[mt][2], fAh[mt][3]);
                    ldsm4t(tAl + aA[s][mt], fAl[mt][0], fAl[mt][1], fAl[mt][2], fAl[mt][3]);
                }
            }
            #pragma unroll
            for (int j = 0; j < 2; j++) {
                if (!TB) {
                    ldsm4t(tBh + aB[s][j], fBh[2*j][0], fBh[2*j][1], fBh[2*j+1][0], fBh[2*j+1][1]);
                    ldsm4t(tBl + aB[s][j], fBl[2*j][0], fBl[2*j][1], fBl[2*j+1][0], fBl[2*j+1][1]);
                } else {
                    ldsm4 (tBh + aB[s][j], fBh[2*j][0], fBh[2*j][1], fBh[2*j+1][0], fBh[2*j+1][1]);
                    ldsm4 (tBl + aB[s][j], fBl[2*j][0], fBl[2*j][1], fBl[2*j+1][0], fBl[2*j+1][1]);
                }
            }
            #pragma unroll
            for (int mt = 0; mt < MT; mt++)
                #pragma unroll
                for (int nt = 0; nt < 4; nt++) {
                    mma16816(acc[mt][nt], fAh[mt], fBh[nt]);
                    mma16816(acc[mt][nt], fAh[mt], fBl[nt]);
                    mma16816(acc[mt][nt], fAl[mt], fBh[nt]);
                }
        }
        if (c + 1 < NC) {
            uint32_t b1 = (buf ^ 1) * BUF;
            #pragma unroll
            for (int i = 0; i < AI; i++) {
                uint2 h, l; cvt_split(sa[i], h, l);
                *(uint2*)(smem + b1 + aoff[i])       = h;
                *(uint2*)(smem + b1 + A_T + aoff[i]) = l;
            }
            #pragma unroll
            for (int i = 0; i < 4; i++) {
                uint2 h, l; cvt_split(sb[i], h, l);
                *(uint2*)(smem + b1 + 2*A_T + boff[i])       = h;
                *(uint2*)(smem + b1 + 2*A_T + B_T + boff[i]) = l;
            }
        }
        __syncthreads();
    }

    #pragma unroll
    for (int mt = 0; mt < MT; mt++) {
        #pragma unroll
        for (int half = 0; half < 2; half++) {
            int r = m0 + wm + mt * 16 + (lane >> 2) + half * 8;
            #pragma unroll
            for (int nt = 0; nt < 4; nt++) {
                int cc = n0 + wn + nt * 8 + 2 * (lane & 3);
                float v0 = acc[mt][nt][half * 2 + 0];
                float v1 = acc[mt][nt][half * 2 + 1];
                size_t idx = (size_t)r * ldc + cc;
                if (EPI == 0) {
                    *(float2*)(C + idx) = make_float2(v0, v1);
                } else if (EPI == 1) {
                    *(float2*)(C + idx) = make_float2(v0, v1);
                    *(float2*)(out2 + idx) = make_float2(gelu_f(v0), gelu_f(v1));
                } else if (EPI == 2) {
                    float2 a2 = *(const float2*)(aux + idx);
                    *(float2*)(C + idx) = make_float2((v0 - a2.x) * scale, (v1 - a2.y) * scale);
                } else if (EPI == 3) {
                    float2 a2 = *(const float2*)(aux + idx);
                    *(float2*)(C + idx) = make_float2(v0 * gelu_grad_f(a2.x), v1 * gelu_grad_f(a2.y));
                } else if (EPI == 6) {   // fused momentum update: C=W, S=state, v=grad
                    float2 w = *(const float2*)(C + idx);
                    float2 s = *(const float2*)(S + idx);
                    float s0 = decay * s.x - lr * v0;
                    float s1 = decay * s.y - lr * v1;
                    *(float2*)(S + idx) = make_float2(s0, s1);
                    *(float2*)(C + idx) = make_float2(om * w.x + s0, om * w.y + s1);
                }
            }
        }
    }
}

// ---------------- software grid barrier --------------------------------------
__device__ __forceinline__ void gsync(unsigned& epoch) {
    __syncthreads();
    if (threadIdx.x == 0) {
        __threadfence();
        epoch++;
        atomicAdd(&g_arrive, 1u);
        const unsigned target = epoch * NB;
        while (__ldcg(&g_arrive) < target) __nanosleep(64);
        __threadfence();
    }
    __syncthreads();
}

// ---------------- persistent chunk loop --------------------------------------
__global__ void __launch_bounds__(256, 1)
chunk_loop(const float* __restrict__ alpha_t, const float* __restrict__ lr_t,
           const float* __restrict__ decay_t, const int* __restrict__ upd)
{
    if (*upd == 0) return;
    const float alpha = sigmoid_f(*alpha_t);
    const float lr    = sigmoid_f(*lr_t);
    const float decay = sigmoid_f(*decay_t);
    const float om    = 1.0f - alpha;
    const float escale = 2.0f / (float)(ROWS_CHUNK * D_IN);

    extern __shared__ char smem[];
    const uint32_t sbase = smem_u32(smem);
    const int tid = threadIdx.x;
    unsigned epoch = 0;

    for (int c = 0; c < NCHUNK; c++) {
        const float* Kc = g_K + (size_t)c * ROWS_CHUNK * D_IN;
        const float* Vc = g_V + (size_t)c * ROWS_CHUNK * D_IN;

        // P1: H = Kc @ W1 ; A = gelu(H)   [1024x1024] K=512, BM=64 -> 128 tiles
        for (int t = blockIdx.x; t < 128; t += NB)
            tile_gemm<64,false,false,1>(Kc, D_IN, g_W1, HID, g_H, HID, D_IN,
                nullptr, g_A, 0.f, (t >> 3) * 64, (t & 7) * 128, smem, sbase,
                0.f, 0.f, 0.f, nullptr);
        gsync(epoch);

        // P2: E = (A @ W2 - Vc)*escale    [1024x512] K=1024, BM=32 -> 128 tiles
        for (int t = blockIdx.x; t < 128; t += NB)
            tile_gemm<32,false,false,2>(g_A, HID, g_W2, D_IN, g_E, D_IN, HID,
                Vc, nullptr, escale, (t >> 2) * 32, (t & 3) * 128, smem, sbase,
                0.f, 0.f, 0.f, nullptr);
        gsync(epoch);

        // P3: dH = (E @ W2^T)*gelu'(H)  [1024x1024] K=512, BM=64 -> 128 tiles
        //     G2 = A^T @ E              [1024x512] K=1024, BM=32 -> 128 tiles
        for (int t = blockIdx.x; t < 256; t += NB) {
            if (t < 128)
                tile_gemm<64,false,true,3>(g_E, D_IN, g_W2, D_IN, g_dH, HID, D_IN,
                    g_H, nullptr, 0.f, (t >> 3) * 64, (t & 7) * 128, smem, sbase,
                    0.f, 0.f, 0.f, nullptr);
            else {
                int u = t - 128;
                tile_gemm<32,true,false,0>(g_A, HID, g_E, D_IN, g_G2, D_IN, ROWS_CHUNK,
                    nullptr, nullptr, 0.f, (u >> 2) * 32, (u & 3) * 128, smem, sbase,
                    0.f, 0.f, 0.f, nullptr);
            }
        }
        gsync(epoch);

        // P4: W2/S2 elementwise update (uses G2), then G1 with fused W1/S1 update
        for (int i = blockIdx.x * 256 + tid; i < WSZ; i += NB * 256) {
            float s2 = decay * g_S2[i] - lr * g_G2[i];
            g_S2[i] = s2;
            g_W2[i] = om * g_W2[i] + s2;
        }
        // G1 = Kc^T @ dH  [512x1024] K=1024, BM=32 -> 128 tiles (EPI=6: update W1)
        for (int t = blockIdx.x; t < 128; t += NB)
            tile_gemm<32,true,false,6>(Kc, D_IN, g_dH, HID, g_W1, HID, ROWS_CHUNK,
                nullptr, nullptr, 0.f, (t >> 3) * 32, (t & 7) * 128, smem, sbase,
                decay, lr, om, g_S1);
        gsync(epoch);
    }
}

// ---------------- init: W <- mem_w, S <- 0, barrier reset --------------------
__global__ void init_kernel(const float* __restrict__ w1, const float* __restrict__ w2) {
    int i = blockIdx.x * 256 + threadIdx.x;
    if (i == 0) g_arrive = 0;
    if (i < WSZ) {
        g_W1[i] = w1[i];
        g_W2[i] = w2[i];
        g_S1[i] = 0.0f;
        g_S2[i] = 0.0f;
    }
}

// ---------------- launcher ---------------------------------------------------
extern "C" void kernel_launch(void* const* d_in, const int* in_sizes, int n_in,
                              void* d_out, int out_size)
{
    const float* x       = (const float*)d_in[0];
    const float* w_q     = (const float*)d_in[1];
    const float* w_k     = (const float*)d_in[2];
    const float* w_v     = (const float*)d_in[3];
    const float* mem_w1  = (const float*)d_in[4];
    const float* mem_w2  = (const float*)d_in[5];
    const float* alpha_t = (const float*)d_in[6];
    const float* lr_t    = (const float*)d_in[7];
    const float* decay_t = (const float*)d_in[8];
    const int*   upd     = (const int*)d_in[9];
    float* out = (float*)d_out;

    float *Q, *K, *V, *W1, *W2, *Hq;
    cudaGetSymbolAddress((void**)&Q,  g_Q);
    cudaGetSymbolAddress((void**)&K,  g_K);
    cudaGetSymbolAddress((void**)&V,  g_V);
    cudaGetSymbolAddress((void**)&W1, g_W1);
    cudaGetSymbolAddress((void**)&W2, g_W2);
    cudaGetSymbolAddress((void**)&Hq, g_Hq);

    cudaFuncSetAttribute(hgemm<false,false,0>, cudaFuncAttributeMaxDynamicSharedMemorySize, SMEM_BYTES);
    cudaFuncSetAttribute(hgemm<false,false,4>, cudaFuncAttributeMaxDynamicSharedMemorySize, SMEM_BYTES);
    cudaFuncSetAttribute(hgemm<false,false,5>, cudaFuncAttributeMaxDynamicSharedMemorySize, SMEM_BYTES);
    cudaFuncSetAttribute(chunk_loop, cudaFuncAttributeMaxDynamicSharedMemorySize, P_SMEM);

    const dim3 thr(256);

    init_kernel<<<WSZ / 256, thr>>>(mem_w1, mem_w2);

    // Q = x @ w_q ; K,V = x @ w_{k,v} (chunk-major permuted store)
    {
        dim3 g(D_IN / 128, ROWS_TOTAL / 128);
        hgemm<false,false,0><<<g, thr, SMEM_BYTES>>>(x, D_IN, w_q, D_IN, Q, D_IN, D_IN, nullptr, nullptr, 0.f);
        hgemm<false,false,5><<<g, thr, SMEM_BYTES>>>(x, D_IN, w_k, D_IN, K, D_IN, D_IN, nullptr, nullptr, 0.f);
        hgemm<false,false,5><<<g, thr, SMEM_BYTES>>>(x, D_IN, w_v, D_IN, V, D_IN, D_IN, nullptr, nullptr, 0.f);
    }

    // Entire 16-chunk memory-update loop: one persistent kernel
    chunk_loop<<<NB, thr, P_SMEM>>>(alpha_t, lr_t, decay_t, upd);

    // Readout: Hq = gelu(Q @ W1) ; out = Hq @ W2
    {
        dim3 g1(HID / 128, ROWS_TOTAL / 128);
        hgemm<false,false,4><<<g1, thr, SMEM_BYTES>>>(Q, D_IN, W1, HID, Hq, HID, D_IN, nullptr, nullptr, 0.f);
        dim3 g2(D_IN / 128, ROWS_TOTAL / 128);
        hgemm<false,false,0><<<g2, thr, SMEM_BYTES>>>(Hq, HID, W2, D_IN, out, D_IN, HID, nullptr, nullptr, 0.f);
    }
    (void)in_sizes; (void)n_in; (void)out_size;
}

// round 5
// speedup vs baseline: 3.1883x; 1.2057x over previous
#include <cuda_runtime.h>
#include <cuda_fp16.h>
#include <cstdint>
#include <math.h>

// ---------------- problem constants ----------------------------------------
#define D_IN   512
#define HID    1024
#define SEQ    4096
#define BATCH  4
#define CHUNK  256
#define NCHUNK 16
#define ROWS_TOTAL (BATCH*SEQ)     // 16384
#define ROWS_CHUNK (BATCH*CHUNK)   // 1024
#define WSZ    (D_IN*HID)          // 524288
#define NB     148

// ---------------- scratch (device globals) ----------------------------------
// fp32 masters / aux
__device__ float g_V [ROWS_TOTAL*D_IN];   // chunk-major f32 (aux for E)
__device__ float g_H [ROWS_CHUNK*HID];    // pre-gelu (aux for dH)
__device__ float g_G2[WSZ];
__device__ float g_W1[WSZ];
__device__ float g_W2[WSZ];
__device__ float g_S1[WSZ];
__device__ float g_S2[WSZ];
__device__ unsigned g_arrive;
// split fp16 operand arrays (hi, lo)
__device__ __half g_xh [ROWS_TOTAL*D_IN], g_xl [ROWS_TOTAL*D_IN];
__device__ __half g_Qh [ROWS_TOTAL*D_IN], g_Ql [ROWS_TOTAL*D_IN];
__device__ __half g_Kh [ROWS_TOTAL*D_IN], g_Kl [ROWS_TOTAL*D_IN];  // chunk-major
__device__ __half g_W1h[WSZ], g_W1l[WSZ];
__device__ __half g_W2h[WSZ], g_W2l[WSZ];
__device__ __half g_Ah [ROWS_CHUNK*HID],  g_Al [ROWS_CHUNK*HID];
__device__ __half g_Eh [ROWS_CHUNK*D_IN], g_El [ROWS_CHUNK*D_IN];
__device__ __half g_dHh[ROWS_CHUNK*HID],  g_dHl[ROWS_CHUNK*HID];
__device__ __half g_Hqh[ROWS_TOTAL*HID],  g_Hql[ROWS_TOTAL*HID];
__device__ __half g_wqh[D_IN*D_IN], g_wql[D_IN*D_IN];
__device__ __half g_wkh[D_IN*D_IN], g_wkl[D_IN*D_IN];
__device__ __half g_wvh[D_IN*D_IN], g_wvl[D_IN*D_IN];

// ---------------- math helpers ----------------------------------------------
__device__ __forceinline__ float gelu_f(float x) {
    return 0.5f * x * (1.0f + erff(x * 0.70710678118654752f));
}
__device__ __forceinline__ float gelu_grad_f(float x) {
    float cdf = 0.5f * (1.0f + erff(x * 0.70710678118654752f));
    float pdf = 0.3989422804014327f * __expf(-0.5f * x * x);
    return cdf + x * pdf;
}
__device__ __forceinline__ float sigmoid_f(float x) {
    return 1.0f / (1.0f + __expf(-x));
}
__device__ __forceinline__ void split2(float v0, float v1, uint32_t& h, uint32_t& l) {
    __half2 hh = __floats2half2_rn(v0, v1);
    float2 hf = __half22float2(hh);
    __half2 ll = __floats2half2_rn(v0 - hf.x, v1 - hf.y);
    h = *(uint32_t*)&hh;
    l = *(uint32_t*)&ll;
}

// ---------------- PTX helpers ------------------------------------------------
__device__ __forceinline__ uint32_t smem_u32(const void* p) {
    uint32_t a;
    asm("{ .reg .u64 t; cvta.to.shared.u64 t, %1; cvt.u32.u64 %0, t; }" : "=r"(a) : "l"(p));
    return a;
}
__device__ __forceinline__ void cp16(uint32_t d, const void* s) {
    asm volatile("cp.async.cg.shared.global [%0], [%1], 16;" :: "r"(d), "l"(s));
}
__device__ __forceinline__ void cp_commit() {
    asm volatile("cp.async.commit_group;");
}
__device__ __forceinline__ void ldsm4(uint32_t a, uint32_t& r0, uint32_t& r1,
                                      uint32_t& r2, uint32_t& r3) {
    asm volatile("ldmatrix.sync.aligned.m8n8.x4.shared.b16 {%0,%1,%2,%3}, [%4];"
                 : "=r"(r0), "=r"(r1), "=r"(r2), "=r"(r3) : "r"(a));
}
__device__ __forceinline__ void ldsm4t(uint32_t a, uint32_t& r0, uint32_t& r1,
                                       uint32_t& r2, uint32_t& r3) {
    asm volatile("ldmatrix.sync.aligned.m8n8.x4.trans.shared.b16 {%0,%1,%2,%3}, [%4];"
                 : "=r"(r0), "=r"(r1), "=r"(r2), "=r"(r3) : "r"(a));
}
__device__ __forceinline__ void mma16816(float* c, const uint32_t* a, const uint32_t* b) {
    asm volatile(
        "mma.sync.aligned.m16n8k16.row.col.f32.f16.f16.f32 "
        "{%0,%1,%2,%3}, {%4,%5,%6,%7}, {%8,%9}, {%0,%1,%2,%3};"
        : "+f"(c[0]), "+f"(c[1]), "+f"(c[2]), "+f"(c[3])
        : "r"(a[0]), "r"(a[1]), "r"(a[2]), "r"(a[3]), "r"(b[0]), "r"(b[1]));
}

// ============================================================================
// Unified split-fp16 tile GEMM. Tile BM x 128, BK=32, 8 warps (2m x 4n),
// warp tile (BM/2) x 32. Operands are pre-split hi/lo fp16 arrays in gmem,
// staged via cp.async (no conversion, no register staging).
// TA=false: A[M][K] halfs (lda=K).  TA=true: A[K][M] halfs (lda=M).
// TB=false: B[K][N] halfs (ldb=N).  TB=true: B[N][K] halfs (ldb=K).
// EPI: 0 C=v(f32) | 1 C=v(f32), Ch/Cl=split(gelu(v)) | 2 Ch/Cl=split((v-aux)*scale)
//      3 Ch/Cl=split(v*gelu'(aux)) | 4 Ch/Cl=split(gelu(v))
//      6 fused momentum: s=decay*S-lr*v; S=s; w=om*C+s; C=w; Ch/Cl=split(w)
//      7 Ch/Cl=split(v) | 8 perm: Ch/Cl=split(v) | 9 perm: C=v(f32)
// ============================================================================
#define P_SMEM 49152

template<int BM, bool TA, bool TB, int EPI>
__device__ __forceinline__ void tile_gemm(
    const __half* __restrict__ Ah_, const __half* __restrict__ Al_, int lda,
    const __half* __restrict__ Bh_, const __half* __restrict__ Bl_, int ldb,
    int K, int m0, int n0, uint32_t sbase,
    float* __restrict__ C, __half* __restrict__ Ch, __half* __restrict__ Cl, int ldc,
    const float* __restrict__ aux, float scale,
    float decay, float lr, float om, float* __restrict__ S)
{
    constexpr int A_T = BM * 64;          // bytes per A half-tile
    constexpr int B_T = 8192;
    constexpr int BUF = 2 * A_T + 2 * B_T;
    constexpr int MT  = BM / 32;

    const int tid = threadIdx.x, wid = tid >> 5, lane = tid & 31;
    const int wm = (wid & 1) * (BM / 2);
    const int wn = (wid >> 1) * 32;

    float acc[MT][4][4];
    #pragma unroll
    for (int a = 0; a < MT; a++)
        #pragma unroll
        for (int b = 0; b < 4; b++)
            #pragma unroll
            for (int d = 0; d < 4; d++) acc[a][b][d] = 0.f;

    // ---- staging setup ----
    const __half *srcA0 = nullptr, *srcA1 = nullptr;
    uint32_t dA0 = 0, dA1 = 0;
    if (!TA) {
        if (BM == 64) {
            int r = tid >> 2, kq = tid & 3;
            size_t o = (size_t)(m0 + r) * lda + kq * 8;
            srcA0 = Ah_ + o; srcA1 = Al_ + o;
            uint32_t off = r * 64 + ((kq ^ ((r >> 1) & 3)) << 4);
            dA0 = off; dA1 = A_T + off;
        } else {
            int fi = tid & 127, r = fi >> 2, kq = fi & 3;
            size_t o = (size_t)(m0 + r) * lda + kq * 8;
            bool hi = tid < 128;
            srcA0 = (hi ? Ah_ : Al_) + o;
            dA0 = (hi ? 0u : (uint32_t)A_T) + r * 64 + ((kq ^ ((r >> 1) & 3)) << 4);
        }
    } else {
        if (BM == 64) {
            int kr = tid >> 3, rq = tid & 7;
            size_t o = (size_t)kr * lda + m0 + rq * 8;
            srcA0 = Ah_ + o; srcA1 = Al_ + o;
            uint32_t off = kr * 128 + ((rq ^ (kr & 7)) << 4);
            dA0 = off; dA1 = A_T + off;
        } else {
            int fi = tid & 127, kr = fi >> 2, rq = fi & 3;
            size_t o = (size_t)kr * lda + m0 + rq * 8;
            bool hi = tid < 128;
            srcA0 = (hi ? Ah_ : Al_) + o;
            dA0 = (hi ? 0u : (uint32_t)A_T) + kr * 64 + ((rq ^ (kr & 3)) << 4);
        }
    }
    const size_t advA = TA ? (size_t)32 * lda : 32;

    const __half *srcBh[2], *srcBl[2];
    uint32_t dB[2];
    #pragma unroll
    for (int i = 0; i < 2; i++) {
        int fi = tid + i * 256;
        size_t o;
        if (!TB) {
            int kr = fi >> 4, rq = fi & 15;
            o = (size_t)kr * ldb + n0 + rq * 8;
            dB[i] = 2 * A_T + kr * 256 + ((rq ^ (kr & 7)) << 4);
        } else {
            int r = fi >> 2, kq = fi & 3;
            o = (size_t)(n0 + r) * ldb + kq * 8;
            dB[i] = 2 * A_T + r * 64 + ((kq ^ ((r >> 1) & 3)) << 4);
        }
        srcBh[i] = Bh_ + o; srcBl[i] = Bl_ + o;
    }
    const size_t advB = TB ? 32 : (size_t)32 * ldb;

    // ---- ldmatrix addresses (relative to buffer base) ----
    uint32_t aA[2][MT], aB[2][2];
    #pragma unroll
    for (int s = 0; s < 2; s++) {
        #pragma unroll
        for (int mt = 0; mt < MT; mt++) {
            if (!TA) {
                int r = wm + mt * 16 + (lane & 15);
                int g = 2 * s + (lane >> 4);
                aA[s][mt] = r * 64 + ((g ^ ((r >> 1) & 3)) << 4);
            } else {
                int k = 16 * s + (lane & 7) + (lane >> 4) * 8;
                int mg = ((wm + mt * 16) >> 3) + ((lane >> 3) & 1);
                aA[s][mt] = (BM == 64) ? k * 128 + ((mg ^ (k & 7)) << 4)
                                       : k * 64  + ((mg ^ (k & 3)) << 4);
            }
        }
        #pragma unroll
        for (int j = 0; j < 2; j++) {
            if (!TB) {
                int k = 16 * s + (lane & 7) + ((lane >> 3) & 1) * 8;
                int ng = ((wn + j * 16) >> 3) + (lane >> 4);
                aB[s][j] = k * 256 + ((ng ^ (k & 7)) << 4);
            } else {
                int n = wn + j * 16 + (lane & 7) + (lane >> 4) * 8;
                int g = 2 * s + ((lane >> 3) & 1);
                aB[s][j] = n * 64 + ((g ^ ((n >> 1) & 3)) << 4);
            }
        }
    }

    const int NC = K >> 5;

    // issue helper (macro-ish lambda)
    auto issue = [&](int c, int buf) {
        uint32_t b = sbase + buf * BUF;
        if (BM == 64) {
            cp16(b + dA0, srcA0 + c * advA);
            cp16(b + dA1, srcA1 + c * advA);
        } else {
            cp16(b + dA0, srcA0 + c * advA);
        }
        #pragma unroll
        for (int i = 0; i < 2; i++) {
            cp16(b + dB[i],       srcBh[i] + c * advB);
            cp16(b + dB[i] + B_T, srcBl[i] + c * advB);
        }
        cp_commit();
    };

    issue(0, 0);
    for (int c = 0; c < NC; c++) {
        const int buf = c & 1;
        if (c + 1 < NC) {
            issue(c + 1, buf ^ 1);
            asm volatile("cp.async.wait_group 1;");
        } else {
            asm volatile("cp.async.wait_group 0;");
        }
        __syncthreads();

        const uint32_t bb = sbase + buf * BUF;
        uint32_t FAh[2][MT][4], FAl[2][MT][4], FBh[2][4][2], FBl[2][4][2];
        #pragma unroll
        for (int s = 0; s < 2; s++) {
            #pragma unroll
            for (int mt = 0; mt < MT; mt++) {
                if (!TA) {
                    ldsm4 (bb + aA[s][mt],       FAh[s][mt][0], FAh[s][mt][1], FAh[s][mt][2], FAh[s][mt][3]);
                    ldsm4 (bb + A_T + aA[s][mt], FAl[s][mt][0], FAl[s][mt][1], FAl[s][mt][2], FAl[s][mt][3]);
                } else {
                    ldsm4t(bb + aA[s][mt],       FAh[s][mt][0], FAh[s][mt][1], FAh[s][mt][2], FAh[s][mt][3]);
                    ldsm4t(bb + A_T + aA[s][mt], FAl[s][mt][0], FAl[s][mt][1], FAl[s][mt][2], FAl[s][mt][3]);
                }
            }
            #pragma unroll
            for (int j = 0; j < 2; j++) {
                if (!TB) {
                    ldsm4t(bb + 2*A_T + aB[s][j],       FBh[s][2*j][0], FBh[s][2*j][1], FBh[s][2*j+1][0], FBh[s][2*j+1][1]);
                    ldsm4t(bb + 2*A_T + B_T + aB[s][j], FBl[s][2*j][0], FBl[s][2*j][1], FBl[s][2*j+1][0], FBl[s][2*j+1][1]);
                } else {
                    ldsm4 (bb + 2*A_T + aB[s][j],       FBh[s][2*j][0], FBh[s][2*j][1], FBh[s][2*j+1][0], FBh[s][2*j+1][1]);
                    ldsm4 (bb + 2*A_T + B_T + aB[s][j], FBl[s][2*j][0], FBl[s][2*j][1], FBl[s][2*j+1][0], FBl[s][2*j+1][1]);
                }
            }
        }
        #pragma unroll
        for (int s = 0; s < 2; s++)
            #pragma unroll
            for (int mt = 0; mt < MT; mt++)
                #pragma unroll
                for (int nt = 0; nt < 4; nt++) {
                    mma16816(acc[mt][nt], FAh[s][mt], FBh[s][nt]);
                    mma16816(acc[mt][nt], FAh[s][mt], FBl[s][nt]);
                    mma16816(acc[mt][nt], FAl[s][mt], FBh[s][nt]);
                }
        __syncthreads();
    }

    // ---- epilogue ----
    #pragma unroll
    for (int mt = 0; mt < MT; mt++) {
        #pragma unroll
        for (int half = 0; half < 2; half++) {
            int r = m0 + wm + mt * 16 + (lane >> 2) + half * 8;
            #pragma unroll
            for (int nt = 0; nt < 4; nt++) {
                int cc = n0 + wn + nt * 8 + 2 * (lane & 3);
                float v0 = acc[mt][nt][half * 2 + 0];
                float v1 = acc[mt][nt][half * 2 + 1];
                size_t idx = (size_t)r * ldc + cc;
                if (EPI == 0) {
                    *(float2*)(C + idx) = make_float2(v0, v1);
                } else if (EPI == 1) {
                    *(float2*)(C + idx) = make_float2(v0, v1);
                    uint32_t h, l; split2(gelu_f(v0), gelu_f(v1), h, l);
                    *(uint32_t*)(Ch + idx) = h; *(uint32_t*)(Cl + idx) = l;
                } else if (EPI == 2) {
                    float2 a2 = *(const float2*)(aux + idx);
                    uint32_t h, l; split2((v0 - a2.x) * scale, (v1 - a2.y) * scale, h, l);
                    *(uint32_t*)(Ch + idx) = h; *(uint32_t*)(Cl + idx) = l;
                } else if (EPI == 3) {
                    float2 a2 = *(const float2*)(aux + idx);
                    uint32_t h, l; split2(v0 * gelu_grad_f(a2.x), v1 * gelu_grad_f(a2.y), h, l);
                    *(uint32_t*)(Ch + idx) = h; *(uint32_t*)(Cl + idx) = l;
                } else if (EPI == 4) {
                    uint32_t h, l; split2(gelu_f(v0), gelu_f(v1), h, l);
                    *(uint32_t*)(Ch + idx) = h; *(uint32_t*)(Cl + idx) = l;
                } else if (EPI == 6) {
                    float2 w = *(const float2*)(C + idx);
                    float2 s = *(const float2*)(S + idx);
                    float s0 = decay * s.x - lr * v0;
                    float s1 = decay * s.y - lr * v1;
                    float w0 = om * w.x + s0, w1 = om * w.y + s1;
                    *(float2*)(S + idx) = make_float2(s0, s1);
                    *(float2*)(C + idx) = make_float2(w0, w1);
                    uint32_t h, l; split2(w0, w1, h, l);
                    *(uint32_t*)(Ch + idx) = h; *(uint32_t*)(Cl + idx) = l;
                } else if (EPI == 7) {
                    uint32_t h, l; split2(v0, v1, h, l);
                    *(uint32_t*)(Ch + idx) = h; *(uint32_t*)(Cl + idx) = l;
                } else if (EPI == 8) {
                    int b = r >> 12, sq = r & 4095, chn = sq >> 8, t = sq & 255;
                    size_t orow = (size_t)(chn * 1024 + b * 256 + t) * ldc + cc;
                    uint32_t h, l; split2(v0, v1, h, l);
                    *(uint32_t*)(Ch + orow) = h; *(uint32_t*)(Cl + orow) = l;
                } else { // EPI == 9
                    int b = r >> 12, sq = r & 4095, chn = sq >> 8, t = sq & 255;
                    size_t orow = (size_t)(chn * 1024 + b * 256 + t) * ldc + cc;
                    *(float2*)(C + orow) = make_float2(v0, v1);
                }
            }
        }
    }
}

// ---------------- standalone wrappers ---------------------------------------
__global__ void __launch_bounds__(256) qkv_kernel() {
    extern __shared__ char smem[];
    const uint32_t sbase = smem_u32(smem);
    int m0 = blockIdx.y * 64, n0 = blockIdx.x * 128;
    int z = blockIdx.z;
    if (z == 0)
        tile_gemm<64,false,false,7>(g_xh, g_xl, D_IN, g_wqh, g_wql, D_IN, D_IN,
            m0, n0, sbase, nullptr, g_Qh, g_Ql, D_IN, nullptr, 0.f, 0.f, 0.f, 0.f, nullptr);
    else if (z == 1)
        tile_gemm<64,false,false,8>(g_xh, g_xl, D_IN, g_wkh, g_wkl, D_IN, D_IN,
            m0, n0, sbase, nullptr, g_Kh, g_Kl, D_IN, nullptr, 0.f, 0.f, 0.f, 0.f, nullptr);
    else
        tile_gemm<64,false,false,9>(g_xh, g_xl, D_IN, g_wvh, g_wvl, D_IN, D_IN,
            m0, n0, sbase, g_V, nullptr, nullptr, D_IN, nullptr, 0.f, 0.f, 0.f, 0.f, nullptr);
}

__global__ void __launch_bounds__(256) ro1_kernel() {
    extern __shared__ char smem[];
    const uint32_t sbase = smem_u32(smem);
    tile_gemm<64,false,false,4>(g_Qh, g_Ql, D_IN, g_W1h, g_W1l, HID, D_IN,
        blockIdx.y * 64, blockIdx.x * 128, sbase,
        nullptr, g_Hqh, g_Hql, HID, nullptr, 0.f, 0.f, 0.f, 0.f, nullptr);
}

__global__ void __launch_bounds__(256) ro2_kernel(float* __restrict__ out) {
    extern __shared__ char smem[];
    const uint32_t sbase = smem_u32(smem);
    tile_gemm<64,false,false,0>(g_Hqh, g_Hql, HID, g_W2h, g_W2l, D_IN, HID,
        blockIdx.y * 64, blockIdx.x * 128, sbase,
        out, nullptr, nullptr, D_IN, nullptr, 0.f, 0.f, 0.f, 0.f, nullptr);
}

// ---------------- software grid barrier --------------------------------------
__device__ __forceinline__ void gsync(unsigned& epoch) {
    __syncthreads();
    if (threadIdx.x == 0) {
        __threadfence();
        epoch++;
        atomicAdd(&g_arrive, 1u);
        const unsigned target = epoch * NB;
        while (__ldcg(&g_arrive) < target) __nanosleep(64);
        __threadfence();
    }
    __syncthreads();
}

// ---------------- persistent chunk loop --------------------------------------
__global__ void __launch_bounds__(256, 1)
chunk_loop(const float* __restrict__ alpha_t, const float* __restrict__ lr_t,
           const float* __restrict__ decay_t, const int* __restrict__ upd)
{
    if (*upd == 0) return;
    const float alpha = sigmoid_f(*alpha_t);
    const float lr    = sigmoid_f(*lr_t);
    const float decay = sigmoid_f(*decay_t);
    const float om    = 1.0f - alpha;
    const float escale = 2.0f / (float)(ROWS_CHUNK * D_IN);

    extern __shared__ char smem[];
    const uint32_t sbase = smem_u32(smem);
    const int tid = threadIdx.x;
    unsigned epoch = 0;

    for (int c = 0; c < NCHUNK; c++) {
        const __half* Kch = g_Kh + (size_t)c * ROWS_CHUNK * D_IN;
        const __half* Kcl = g_Kl + (size_t)c * ROWS_CHUNK * D_IN;
        const float*  Vc  = g_V  + (size_t)c * ROWS_CHUNK * D_IN;

        // P1: H = Kc @ W1 (f32) ; A = split(gelu(H))   128 tiles BM=64
        for (int t = blockIdx.x; t < 128; t += NB)
            tile_gemm<64,false,false,1>(Kch, Kcl, D_IN, g_W1h, g_W1l, HID, D_IN,
                (t >> 3) * 64, (t & 7) * 128, sbase,
                g_H, g_Ah, g_Al, HID, nullptr, 0.f, 0.f, 0.f, 0.f, nullptr);
        gsync(epoch);

        // P2: E = split((A @ W2 - Vc)*escale)          128 tiles BM=32, K=1024
        for (int t = blockIdx.x; t < 128; t += NB)
            tile_gemm<32,false,false,2>(g_Ah, g_Al, HID, g_W2h, g_W2l, D_IN, HID,
                (t >> 2) * 32, (t & 3) * 128, sbase,
                nullptr, g_Eh, g_El, D_IN, Vc, escale, 0.f, 0.f, 0.f, nullptr);
        gsync(epoch);

        // P3: dH = split((E @ W2^T)*gelu'(H))          128 tiles BM=64
        //     G2 = A^T @ E (f32)                       128 tiles BM=32, K=1024
        for (int t = blockIdx.x; t < 256; t += NB) {
            if (t < 128)
                tile_gemm<64,false,true,3>(g_Eh, g_El, D_IN, g_W2h, g_W2l, D_IN, D_IN,
                    (t >> 3) * 64, (t & 7) * 128, sbase,
                    nullptr, g_dHh, g_dHl, HID, g_H, 0.f, 0.f, 0.f, 0.f, nullptr);
            else {
                int u = t - 128;
                tile_gemm<32,true,false,0>(g_Ah, g_Al, HID, g_Eh, g_El, D_IN, ROWS_CHUNK,
                    (u >> 2) * 32, (u & 3) * 128, sbase,
                    g_G2, nullptr, nullptr, D_IN, nullptr, 0.f, 0.f, 0.f, 0.f, nullptr);
            }
        }
        gsync(epoch);

        // P4: W2/S2 elementwise update (writes f32 + split), and
        //     G1 = Kc^T @ dH with fused W1/S1 update   128 tiles BM=32, K=1024
        for (int i = blockIdx.x * 256 + tid; i < WSZ; i += NB * 256) {
            float s2 = decay * g_S2[i] - lr * g_G2[i];
            g_S2[i] = s2;
            float w = om * g_W2[i] + s2;
            g_W2[i] = w;
            __half h = __float2half_rn(w);
            g_W2h[i] = h;
            g_W2l[i] = __float2half_rn(w - __half2float(h));
        }
        for (int t = blockIdx.x; t < 128; t += NB)
            tile_gemm<32,true,false,6>(Kch, Kcl, D_IN, g_dHh, g_dHl, HID, ROWS_CHUNK,
                (t >> 3) * 32, (t & 7) * 128, sbase,
                g_W1, g_W1h, g_W1l, HID, nullptr, 0.f, decay, lr, om, g_S1);
        gsync(epoch);
    }
}

// ---------------- init / split kernels ---------------------------------------
__global__ void split_kernel(const float* __restrict__ src,
                             __half* __restrict__ h, __half* __restrict__ l, int n4) {
    int i = blockIdx.x * 256 + threadIdx.x;
    if (i >= n4) return;
    float4 v = ((const float4*)src)[i];
    uint32_t h0, l0, h1, l1;
    split2(v.x, v.y, h0, l0);
    split2(v.z, v.w, h1, l1);
    ((uint2*)h)[i] = make_uint2(h0, h1);
    ((uint2*)l)[i] = make_uint2(l0, l1);
}

__global__ void init_kernel(const float* __restrict__ w1, const float* __restrict__ w2) {
    int i = blockIdx.x * 256 + threadIdx.x;
    if (i == 0) g_arrive = 0;
    if (i < WSZ) {
        float a = w1[i], b = w2[i];
        g_W1[i] = a; g_W2[i] = b;
        g_S1[i] = 0.f; g_S2[i] = 0.f;
        __half ha = __float2half_rn(a);
        g_W1h[i] = ha; g_W1l[i] = __float2half_rn(a - __half2float(ha));
        __half hb = __float2half_rn(b);
        g_W2h[i] = hb; g_W2l[i] = __float2half_rn(b - __half2float(hb));
    }
}

// ---------------- launcher ----------------------------------------------------
extern "C" void kernel_launch(void* const* d_in, const int* in_sizes, int n_in,
                              void* d_out, int out_size)
{
    const float* x       = (const float*)d_in[0];
    const float* w_q     = (const float*)d_in[1];
    const float* w_k     = (const float*)d_in[2];
    const float* w_v     = (const float*)d_in[3];
    const float* mem_w1  = (const float*)d_in[4];
    const float* mem_w2  = (const float*)d_in[5];
    const float* alpha_t = (const float*)d_in[6];
    const float* lr_t    = (const float*)d_in[7];
    const float* decay_t = (const float*)d_in[8];
    const int*   upd     = (const int*)d_in[9];
    float* out = (float*)d_out;

    __half *xh, *xl, *wqh, *wql, *wkh, *wkl, *wvh, *wvl;
    cudaGetSymbolAddress((void**)&xh,  g_xh);
    cudaGetSymbolAddress((void**)&xl,  g_xl);
    cudaGetSymbolAddress((void**)&wqh, g_wqh);
    cudaGetSymbolAddress((void**)&wql, g_wql);
    cudaGetSymbolAddress((void**)&wkh, g_wkh);
    cudaGetSymbolAddress((void**)&wkl, g_wkl);
    cudaGetSymbolAddress((void**)&wvh, g_wvh);
    cudaGetSymbolAddress((void**)&wvl, g_wvl);

    cudaFuncSetAttribute(qkv_kernel, cudaFuncAttributeMaxDynamicSharedMemorySize, P_SMEM);
    cudaFuncSetAttribute(ro1_kernel, cudaFuncAttributeMaxDynamicSharedMemorySize, P_SMEM);
    cudaFuncSetAttribute(ro2_kernel, cudaFuncAttributeMaxDynamicSharedMemorySize, P_SMEM);
    cudaFuncSetAttribute(chunk_loop, cudaFuncAttributeMaxDynamicSharedMemorySize, P_SMEM);

    const dim3 thr(256);

    // split inputs to fp16 hi/lo
    {
        int n4 = ROWS_TOTAL * D_IN / 4;
        split_kernel<<<(n4 + 255) / 256, thr>>>(x, xh, xl, n4);
        int w4 = D_IN * D_IN / 4;
        split_kernel<<<(w4 + 255) / 256, thr>>>(w_q, wqh, wql, w4);
        split_kernel<<<(w4 + 255) / 256, thr>>>(w_k, wkh, wkl, w4);
        split_kernel<<<(w4 + 255) / 256, thr>>>(w_v, wvh, wvl, w4);
    }
    init_kernel<<<WSZ / 256, thr>>>(mem_w1, mem_w2);

    // QKV in one launch (z: 0=Q split, 1=K split perm, 2=V f32 perm)
    qkv_kernel<<<dim3(D_IN / 128, ROWS_TOTAL / 64, 3), thr, P_SMEM>>>();

    // 16-chunk memory update loop: one persistent kernel
    chunk_loop<<<NB, thr, P_SMEM>>>(alpha_t, lr_t, decay_t, upd);

    // Readout
    ro1_kernel<<<dim3(HID / 128, ROWS_TOTAL / 64), thr, P_SMEM>>>();
    ro2_kernel<<<dim3(D_IN / 128, ROWS_TOTAL / 64), thr, P_SMEM>>>(out);

    (void)in_sizes; (void)n_in; (void)out_size;
}

// round 6
// speedup vs baseline: 4.5447x; 1.4254x over previous
#include <cuda_runtime.h>
#include <cuda_fp16.h>
#include <cstdint>
#include <math.h>

// ---------------- problem constants ----------------------------------------
#define D_IN   512
#define HID    1024
#define SEQ    4096
#define BATCH  4
#define CHUNK  256
#define NCHUNK 16
#define ROWS_TOTAL (BATCH*SEQ)     // 16384
#define ROWS_CHUNK (BATCH*CHUNK)   // 1024
#define WSZ    (D_IN*HID)          // 524288
#define NB     148

// ---------------- scratch (device globals) ----------------------------------
__device__ float g_V [ROWS_TOTAL*D_IN];   // chunk-major f32
__device__ float g_H [ROWS_CHUNK*HID];    // pre-gelu f32
__device__ float g_W1[WSZ], g_W2[WSZ], g_S1[WSZ], g_S2[WSZ];
__device__ unsigned g_arrive;

__device__ __half g_xh [ROWS_TOTAL*D_IN], g_xl [ROWS_TOTAL*D_IN];
__device__ __half g_Qh [ROWS_TOTAL*D_IN], g_Ql [ROWS_TOTAL*D_IN];
__device__ __half g_Kh [ROWS_TOTAL*D_IN];                 // chunk-major, hi only
__device__ __half g_W1h[WSZ], g_W1l[WSZ];
__device__ __half g_W2hA[WSZ], g_W2hB[WSZ], g_W2l[WSZ];   // hi ping-pong + lo
__device__ __half g_Ah [ROWS_CHUNK*HID];
__device__ __half g_Eh [ROWS_CHUNK*D_IN];
__device__ __half g_dHh[ROWS_CHUNK*HID];
__device__ __half g_Hqh[ROWS_TOTAL*HID], g_Hql[ROWS_TOTAL*HID];
__device__ __half g_wqh[D_IN*D_IN], g_wql[D_IN*D_IN];
__device__ __half g_wkh[D_IN*D_IN], g_wvh[D_IN*D_IN];

// ---------------- math helpers ----------------------------------------------
__device__ __forceinline__ float gelu_f(float x) {
    return 0.5f * x * (1.0f + erff(x * 0.70710678118654752f));
}
__device__ __forceinline__ float gelu_grad_f(float x) {
    float cdf = 0.5f * (1.0f + erff(x * 0.70710678118654752f));
    float pdf = 0.3989422804014327f * __expf(-0.5f * x * x);
    return cdf + x * pdf;
}
__device__ __forceinline__ float sigmoid_f(float x) {
    return 1.0f / (1.0f + __expf(-x));
}
__device__ __forceinline__ void split2(float v0, float v1, uint32_t& h, uint32_t& l) {
    __half2 hh = __floats2half2_rn(v0, v1);
    float2 hf = __half22float2(hh);
    __half2 ll = __floats2half2_rn(v0 - hf.x, v1 - hf.y);
    h = *(uint32_t*)&hh;
    l = *(uint32_t*)&ll;
}
__device__ __forceinline__ uint32_t pack_h2(float v0, float v1) {
    __half2 hh = __floats2half2_rn(v0, v1);
    return *(uint32_t*)&hh;
}

// ---------------- PTX helpers ------------------------------------------------
__device__ __forceinline__ uint32_t smem_u32(const void* p) {
    uint32_t a;
    asm("{ .reg .u64 t; cvta.to.shared.u64 t, %1; cvt.u32.u64 %0, t; }" : "=r"(a) : "l"(p));
    return a;
}
__device__ __forceinline__ void cp16(uint32_t d, const void* s) {
    asm volatile("cp.async.cg.shared.global [%0], [%1], 16;" :: "r"(d), "l"(s));
}
__device__ __forceinline__ void ldsm4(uint32_t a, uint32_t& r0, uint32_t& r1,
                                      uint32_t& r2, uint32_t& r3) {
    asm volatile("ldmatrix.sync.aligned.m8n8.x4.shared.b16 {%0,%1,%2,%3}, [%4];"
                 : "=r"(r0), "=r"(r1), "=r"(r2), "=r"(r3) : "r"(a));
}
__device__ __forceinline__ void ldsm4t(uint32_t a, uint32_t& r0, uint32_t& r1,
                                       uint32_t& r2, uint32_t& r3) {
    asm volatile("ldmatrix.sync.aligned.m8n8.x4.trans.shared.b16 {%0,%1,%2,%3}, [%4];"
                 : "=r"(r0), "=r"(r1), "=r"(r2), "=r"(r3) : "r"(a));
}
__device__ __forceinline__ void mma16816(float* c, const uint32_t* a, const uint32_t* b) {
    asm volatile(
        "mma.sync.aligned.m16n8k16.row.col.f32.f16.f16.f32 "
        "{%0,%1,%2,%3}, {%4,%5,%6,%7}, {%8,%9}, {%0,%1,%2,%3};"
        : "+f"(c[0]), "+f"(c[1]), "+f"(c[2]), "+f"(c[3])
        : "r"(a[0]), "r"(a[1]), "r"(a[2]), "r"(a[3]), "r"(b[0]), "r"(b[1]));
}

#define P_SMEM 49152

// ============================================================================
// Unified tile GEMM. Tile BM x 128, BK=32, 8 warps (2m x 4n).
// TERMS=3: hi/lo split operands, 3 MMA terms. TERMS=1: hi only, 1 term.
// EPI: 0 C=v f32 | 1 Ch,Cl=split(v) | 2 Ch,Cl=split(gelu(v))
//      3 C=v f32, Ch=h(gelu(v)) | 4 Ch=h((v-aux)*scale) | 5 Ch=h(v*gelu'(aux))
//      6 momentum: s=decay*S-lr*v; S=s; w=om*C+s; C=w; Ch,Cl=split(w)
//      7 perm rows, Ch=h(v) | 8 perm rows, C=v f32
// ============================================================================
template<int BM, bool TA, bool TB, int TERMS, int EPI>
__device__ __forceinline__ void tile_gemm(
    const __half* __restrict__ Ah_, const __half* __restrict__ Al_, int lda,
    const __half* __restrict__ Bh_, const __half* __restrict__ Bl_, int ldb,
    int K, int m0, int n0, uint32_t sbase,
    float* __restrict__ C, __half* __restrict__ Ch, __half* __restrict__ Cl, int ldc,
    const float* __restrict__ aux, float scale,
    float decay, float lr, float om, float* __restrict__ S)
{
    constexpr int A_T = BM * 64;
    constexpr int B_T = 8192;
    constexpr int BHI = (TERMS == 3) ? 2 * A_T : A_T;
    constexpr int BUF = BHI + ((TERMS == 3) ? 2 * B_T : B_T);
    constexpr int MT  = BM / 32;

    const int tid = threadIdx.x, wid = tid >> 5, lane = tid & 31;
    const int wm = (wid & 1) * (BM / 2);
    const int wn = (wid >> 1) * 32;

    float acc[MT][4][4];
    #pragma unroll
    for (int a = 0; a < MT; a++)
        #pragma unroll
        for (int b = 0; b < 4; b++)
            #pragma unroll
            for (int d = 0; d < 4; d++) acc[a][b][d] = 0.f;

    // ---- A staging ----
    const __half *srcA0 = nullptr, *srcA1 = nullptr;
    uint32_t dA0 = 0, dA1 = 0;
    bool aAct = true;
    if (TERMS == 3) {
        if (!TA) {
            if (BM == 64) {
                int r = tid >> 2, kq = tid & 3;
                size_t o = (size_t)(m0 + r) * lda + kq * 8;
                srcA0 = Ah_ + o; srcA1 = Al_ + o;
                uint32_t off = r * 64 + ((kq ^ ((r >> 1) & 3)) << 4);
                dA0 = off; dA1 = A_T + off;
            } else {
                int fi = tid & 127, r = fi >> 2, kq = fi & 3;
                size_t o = (size_t)(m0 + r) * lda + kq * 8;
                bool hi = tid < 128;
                srcA0 = (hi ? Ah_ : Al_) + o;
                dA0 = (hi ? 0u : (uint32_t)A_T) + r * 64 + ((kq ^ ((r >> 1) & 3)) << 4);
            }
        } else {
            if (BM == 64) {
                int kr = tid >> 3, rq = tid & 7;
                size_t o = (size_t)kr * lda + m0 + rq * 8;
                srcA0 = Ah_ + o; srcA1 = Al_ + o;
                uint32_t off = kr * 128 + ((rq ^ (kr & 7)) << 4);
                dA0 = off; dA1 = A_T + off;
            } else {
                int fi = tid & 127, kr = fi >> 2, rq = fi & 3;
                size_t o = (size_t)kr * lda + m0 + rq * 8;
                bool hi = tid < 128;
                srcA0 = (hi ? Ah_ : Al_) + o;
                dA0 = (hi ? 0u : (uint32_t)A_T) + kr * 64 + ((rq ^ (kr & 3)) << 4);
            }
        }
    } else {  // TERMS == 1
        if (!TA) {
            if (BM == 64) {
                int r = tid >> 2, kq = tid & 3;
                srcA0 = Ah_ + (size_t)(m0 + r) * lda + kq * 8;
                dA0 = r * 64 + ((kq ^ ((r >> 1) & 3)) << 4);
            } else {
                aAct = tid < 128;
                int r = tid >> 2, kq = tid & 3;
                if (aAct) srcA0 = Ah_ + (size_t)(m0 + r) * lda + kq * 8;
                else      srcA0 = Ah_;
                dA0 = aAct ? (r * 64 + ((kq ^ ((r >> 1) & 3)) << 4)) : 0u;
            }
        } else {
            if (BM == 64) {
                int kr = tid >> 3, rq = tid & 7;
                srcA0 = Ah_ + (size_t)kr * lda + m0 + rq * 8;
                dA0 = kr * 128 + ((rq ^ (kr & 7)) << 4);
            } else {
                aAct = tid < 128;
                int kr = tid >> 2, rq = tid & 3;
                if (aAct) srcA0 = Ah_ + (size_t)kr * lda + m0 + rq * 8;
                else      srcA0 = Ah_;
                dA0 = aAct ? (kr * 64 + ((rq ^ (kr & 3)) << 4)) : 0u;
            }
        }
    }
    const size_t advA = TA ? (size_t)32 * lda : 32;

    // ---- B staging ----
    const __half *srcBh[2], *srcBl[2];
    uint32_t dB[2];
    #pragma unroll
    for (int i = 0; i < 2; i++) {
        int fi = tid + i * 256;
        size_t o;
        if (!TB) {
            int kr = fi >> 4, rq = fi & 15;
            o = (size_t)kr * ldb + n0 + rq * 8;
            dB[i] = BHI + kr * 256 + ((rq ^ (kr & 7)) << 4);
        } else {
            int r = fi >> 2, kq = fi & 3;
            o = (size_t)(n0 + r) * ldb + kq * 8;
            dB[i] = BHI + r * 64 + ((kq ^ ((r >> 1) & 3)) << 4);
        }
        srcBh[i] = Bh_ + o;
        srcBl[i] = (TERMS == 3) ? Bl_ + o : nullptr;
    }
    const size_t advB = TB ? 32 : (size_t)32 * ldb;

    // ---- ldmatrix addresses ----
    uint32_t aA[2][MT], aB[2][2];
    #pragma unroll
    for (int s = 0; s < 2; s++) {
        #pragma unroll
        for (int mt = 0; mt < MT; mt++) {
            if (!TA) {
                int r = wm + mt * 16 + (lane & 15);
                int g = 2 * s + (lane >> 4);
                aA[s][mt] = r * 64 + ((g ^ ((r >> 1) & 3)) << 4);
            } else {
                int k = 16 * s + (lane & 7) + (lane >> 4) * 8;
                int mg = ((wm + mt * 16) >> 3) + ((lane >> 3) & 1);
                aA[s][mt] = (BM == 64) ? k * 128 + ((mg ^ (k & 7)) << 4)
                                       : k * 64  + ((mg ^ (k & 3)) << 4);
            }
        }
        #pragma unroll
        for (int j = 0; j < 2; j++) {
            if (!TB) {
                int k = 16 * s + (lane & 7) + ((lane >> 3) & 1) * 8;
                int ng = ((wn + j * 16) >> 3) + (lane >> 4);
                aB[s][j] = k * 256 + ((ng ^ (k & 7)) << 4);
            } else {
                int n = wn + j * 16 + (lane & 7) + (lane >> 4) * 8;
                int g = 2 * s + ((lane >> 3) & 1);
                aB[s][j] = n * 64 + ((g ^ ((n >> 1) & 3)) << 4);
            }
        }
    }

    const int NC = K >> 5;

    auto issue = [&](int c, int buf) {
        uint32_t b = sbase + buf * BUF;
        if (TERMS == 3) {
            if (BM == 64) {
                cp16(b + dA0, srcA0 + c * advA);
                cp16(b + dA1, srcA1 + c * advA);
            } else {
                cp16(b + dA0, srcA0 + c * advA);
            }
            #pragma unroll
            for (int i = 0; i < 2; i++) {
                cp16(b + dB[i],       srcBh[i] + c * advB);
                cp16(b + dB[i] + B_T, srcBl[i] + c * advB);
            }
        } else {
            if (aAct) cp16(b + dA0, srcA0 + c * advA);
            #pragma unroll
            for (int i = 0; i < 2; i++)
                cp16(b + dB[i], srcBh[i] + c * advB);
        }
        asm volatile("cp.async.commit_group;");
    };

    issue(0, 0);
    for (int c = 0; c < NC; c++) {
        const int buf = c & 1;
        if (c + 1 < NC) {
            issue(c + 1, buf ^ 1);
            asm volatile("cp.async.wait_group 1;");
        } else {
            asm volatile("cp.async.wait_group 0;");
        }
        __syncthreads();

        const uint32_t bb = sbase + buf * BUF;
        uint32_t FAh[2][MT][4], FAl[2][MT][4], FBh[2][4][2], FBl[2][4][2];
        #pragma unroll
        for (int s = 0; s < 2; s++) {
            #pragma unroll
            for (int mt = 0; mt < MT; mt++) {
                if (!TA) {
                    ldsm4 (bb + aA[s][mt], FAh[s][mt][0], FAh[s][mt][1], FAh[s][mt][2], FAh[s][mt][3]);
                    if (TERMS == 3)
                        ldsm4 (bb + A_T + aA[s][mt], FAl[s][mt][0], FAl[s][mt][1], FAl[s][mt][2], FAl[s][mt][3]);
                } else {
                    ldsm4t(bb + aA[s][mt], FAh[s][mt][0], FAh[s][mt][1], FAh[s][mt][2], FAh[s][mt][3]);
                    if (TERMS == 3)
                        ldsm4t(bb + A_T + aA[s][mt], FAl[s][mt][0], FAl[s][mt][1], FAl[s][mt][2], FAl[s][mt][3]);
                }
            }
            #pragma unroll
            for (int j = 0; j < 2; j++) {
                if (!TB) {
                    ldsm4t(bb + BHI + aB[s][j], FBh[s][2*j][0], FBh[s][2*j][1], FBh[s][2*j+1][0], FBh[s][2*j+1][1]);
                    if (TERMS == 3)
                        ldsm4t(bb + BHI + B_T + aB[s][j], FBl[s][2*j][0], FBl[s][2*j][1], FBl[s][2*j+1][0], FBl[s][2*j+1][1]);
                } else {
                    ldsm4 (bb + BHI + aB[s][j], FBh[s][2*j][0], FBh[s][2*j][1], FBh[s][2*j+1][0], FBh[s][2*j+1][1]);
                    if (TERMS == 3)
                        ldsm4 (bb + BHI + B_T + aB[s][j], FBl[s][2*j][0], FBl[s][2*j][1], FBl[s][2*j+1][0], FBl[s][2*j+1][1]);
                }
            }
        }
        #pragma unroll
        for (int s = 0; s < 2; s++)
            #pragma unroll
            for (int mt = 0; mt < MT; mt++)
                #pragma unroll
                for (int nt = 0; nt < 4; nt++) {
                    mma16816(acc[mt][nt], FAh[s][mt], FBh[s][nt]);
                    if (TERMS == 3) {
                        mma16816(acc[mt][nt], FAh[s][mt], FBl[s][nt]);
                        mma16816(acc[mt][nt], FAl[s][mt], FBh[s][nt]);
                    }
                }
        __syncthreads();
    }

    // ---- epilogue ----
    #pragma unroll
    for (int mt = 0; mt < MT; mt++) {
        #pragma unroll
        for (int half = 0; half < 2; half++) {
            int r = m0 + wm + mt * 16 + (lane >> 2) + half * 8;
            #pragma unroll
            for (int nt = 0; nt < 4; nt++) {
                int cc = n0 + wn + nt * 8 + 2 * (lane & 3);
                float v0 = acc[mt][nt][half * 2 + 0];
                float v1 = acc[mt][nt][half * 2 + 1];
                size_t idx = (size_t)r * ldc + cc;
                if (EPI == 0) {
                    *(float2*)(C + idx) = make_float2(v0, v1);
                } else if (EPI == 1) {
                    uint32_t h, l; split2(v0, v1, h, l);
                    *(uint32_t*)(Ch + idx) = h; *(uint32_t*)(Cl + idx) = l;
                } else if (EPI == 2) {
                    uint32_t h, l; split2(gelu_f(v0), gelu_f(v1), h, l);
                    *(uint32_t*)(Ch + idx) = h; *(uint32_t*)(Cl + idx) = l;
                } else if (EPI == 3) {
                    *(float2*)(C + idx) = make_float2(v0, v1);
                    *(uint32_t*)(Ch + idx) = pack_h2(gelu_f(v0), gelu_f(v1));
                } else if (EPI == 4) {
                    float2 a2 = *(const float2*)(aux + idx);
                    *(uint32_t*)(Ch + idx) = pack_h2((v0 - a2.x) * scale, (v1 - a2.y) * scale);
                } else if (EPI == 5) {
                    float2 a2 = *(const float2*)(aux + idx);
                    *(uint32_t*)(Ch + idx) = pack_h2(v0 * gelu_grad_f(a2.x), v1 * gelu_grad_f(a2.y));
                } else if (EPI == 6) {
                    float2 w = *(const float2*)(C + idx);
                    float2 s = *(const float2*)(S + idx);
                    float s0 = decay * s.x - lr * v0;
                    float s1 = decay * s.y - lr * v1;
                    float w0 = om * w.x + s0, w1 = om * w.y + s1;
                    *(float2*)(S + idx) = make_float2(s0, s1);
                    *(float2*)(C + idx) = make_float2(w0, w1);
                    uint32_t h, l; split2(w0, w1, h, l);
                    *(uint32_t*)(Ch + idx) = h; *(uint32_t*)(Cl + idx) = l;
                } else if (EPI == 7) {
                    int b = r >> 12, sq = r & 4095, chn = sq >> 8, t = sq & 255;
                    size_t orow = (size_t)(chn * 1024 + b * 256 + t) * ldc + cc;
                    *(uint32_t*)(Ch + orow) = pack_h2(v0, v1);
                } else { // EPI == 8
                    int b = r >> 12, sq = r & 4095, chn = sq >> 8, t = sq & 255;
                    size_t orow = (size_t)(chn * 1024 + b * 256 + t) * ldc + cc;
                    *(float2*)(C + orow) = make_float2(v0, v1);
                }
            }
        }
    }
}

// ---------------- standalone wrappers ---------------------------------------
__global__ void __launch_bounds__(256) qkv_kernel() {
    extern __shared__ char smem[];
    const uint32_t sbase = smem_u32(smem);
    int m0 = blockIdx.y * 64, n0 = blockIdx.x * 128;
    int z = blockIdx.z;
    if (z == 0)
        tile_gemm<64,false,false,3,1>(g_xh, g_xl, D_IN, g_wqh, g_wql, D_IN, D_IN,
            m0, n0, sbase, nullptr, g_Qh, g_Ql, D_IN, nullptr, 0.f, 0.f, 0.f, 0.f, nullptr);
    else if (z == 1)
        tile_gemm<64,false,false,1,7>(g_xh, nullptr, D_IN, g_wkh, nullptr, D_IN, D_IN,
            m0, n0, sbase, nullptr, g_Kh, nullptr, D_IN, nullptr, 0.f, 0.f, 0.f, 0.f, nullptr);
    else
        tile_gemm<64,false,false,1,8>(g_xh, nullptr, D_IN, g_wvh, nullptr, D_IN, D_IN,
            m0, n0, sbase, g_V, nullptr, nullptr, D_IN, nullptr, 0.f, 0.f, 0.f, 0.f, nullptr);
}

__global__ void __launch_bounds__(256) ro1_kernel() {
    extern __shared__ char smem[];
    const uint32_t sbase = smem_u32(smem);
    tile_gemm<64,false,false,3,2>(g_Qh, g_Ql, D_IN, g_W1h, g_W1l, HID, D_IN,
        blockIdx.y * 64, blockIdx.x * 128, sbase,
        nullptr, g_Hqh, g_Hql, HID, nullptr, 0.f, 0.f, 0.f, 0.f, nullptr);
}

__global__ void __launch_bounds__(256) ro2_kernel(float* __restrict__ out) {
    extern __shared__ char smem[];
    const uint32_t sbase = smem_u32(smem);
    tile_gemm<64,false,false,3,0>(g_Hqh, g_Hql, HID, g_W2hA, g_W2l, D_IN, HID,
        blockIdx.y * 64, blockIdx.x * 128, sbase,
        out, nullptr, nullptr, D_IN, nullptr, 0.f, 0.f, 0.f, 0.f, nullptr);
}

// ---------------- software grid barrier --------------------------------------
__device__ __forceinline__ void gsync(unsigned& epoch) {
    __syncthreads();
    if (threadIdx.x == 0) {
        __threadfence();
        epoch++;
        atomicAdd(&g_arrive, 1u);
        const unsigned target = epoch * NB;
        while (__ldcg(&g_arrive) < target) __nanosleep(32);
        __threadfence();
    }
    __syncthreads();
}

// ---------------- persistent chunk loop --------------------------------------
__global__ void __launch_bounds__(256, 1)
chunk_loop(const float* __restrict__ alpha_t, const float* __restrict__ lr_t,
           const float* __restrict__ decay_t, const int* __restrict__ upd)
{
    if (*upd == 0) return;
    const float alpha = sigmoid_f(*alpha_t);
    const float lr    = sigmoid_f(*lr_t);
    const float decay = sigmoid_f(*decay_t);
    const float om    = 1.0f - alpha;
    const float escale = 2.0f / (float)(ROWS_CHUNK * D_IN);

    extern __shared__ char smem[];
    const uint32_t sbase = smem_u32(smem);
    unsigned epoch = 0;

    for (int c = 0; c < NCHUNK; c++) {
        const __half* Kch = g_Kh + (size_t)c * ROWS_CHUNK * D_IN;
        const float*  Vc  = g_V  + (size_t)c * ROWS_CHUNK * D_IN;
        __half* W2cur = (c & 1) ? g_W2hB : g_W2hA;
        __half* W2nxt = (c & 1) ? g_W2hA : g_W2hB;

        // P1: H = Kc @ W1 (f32), Ah = h(gelu(H))      128 tiles BM=64 K=512
        for (int t = blockIdx.x; t < 128; t += NB)
            tile_gemm<64,false,false,1,3>(Kch, nullptr, D_IN, g_W1h, nullptr, HID, D_IN,
                (t >> 3) * 64, (t & 7) * 128, sbase,
                g_H, g_Ah, nullptr, HID, nullptr, 0.f, 0.f, 0.f, 0.f, nullptr);
        gsync(epoch);

        // P2: Eh = h((A @ W2 - Vc)*escale)            128 tiles BM=32 K=1024
        for (int t = blockIdx.x; t < 128; t += NB)
            tile_gemm<32,false,false,1,4>(g_Ah, nullptr, HID, W2cur, nullptr, D_IN, HID,
                (t >> 2) * 32, (t & 3) * 128, sbase,
                nullptr, g_Eh, nullptr, D_IN, Vc, escale, 0.f, 0.f, 0.f, nullptr);
        gsync(epoch);

        // P3: dHh = h((E @ W2^T) * gelu'(H))          128 tiles BM=64 K=512
        //     G2 = A^T @ E, fused W2/S2 update -> W2nxt  128 tiles BM=32 K=1024
        for (int t = blockIdx.x; t < 256; t += NB) {
            if (t < 128)
                tile_gemm<64,false,true,1,5>(g_Eh, nullptr, D_IN, W2cur, nullptr, D_IN, D_IN,
                    (t >> 3) * 64, (t & 7) * 128, sbase,
                    nullptr, g_dHh, nullptr, HID, g_H, 0.f, 0.f, 0.f, 0.f, nullptr);
            else {
                int u = t - 128;
                tile_gemm<32,true,false,1,6>(g_Ah, nullptr, HID, g_Eh, nullptr, D_IN, ROWS_CHUNK,
                    (u >> 2) * 32, (u & 3) * 128, sbase,
                    g_W2, W2nxt, g_W2l, D_IN, nullptr, 0.f, decay, lr, om, g_S2);
            }
        }
        gsync(epoch);

        // P4: G1 = Kc^T @ dH, fused W1/S1 update      128 tiles BM=32 K=1024
        for (int t = blockIdx.x; t < 128; t += NB)
            tile_gemm<32,true,false,1,6>(Kch, nullptr, D_IN, g_dHh, nullptr, HID, ROWS_CHUNK,
                (t >> 3) * 32, (t & 7) * 128, sbase,
                g_W1, g_W1h, g_W1l, HID, nullptr, 0.f, decay, lr, om, g_S1);
        gsync(epoch);
    }
}

// ---------------- init / convert kernels -------------------------------------
__global__ void split_kernel(const float* __restrict__ src,
                             __half* __restrict__ h, __half* __restrict__ l, int n4) {
    int i = blockIdx.x * 256 + threadIdx.x;
    if (i >= n4) return;
    float4 v = ((const float4*)src)[i];
    uint32_t h0, l0, h1, l1;
    split2(v.x, v.y, h0, l0);
    split2(v.z, v.w, h1, l1);
    ((uint2*)h)[i] = make_uint2(h0, h1);
    ((uint2*)l)[i] = make_uint2(l0, l1);
}
__global__ void half_kernel(const float* __restrict__ src, __half* __restrict__ h, int n4) {
    int i = blockIdx.x * 256 + threadIdx.x;
    if (i >= n4) return;
    float4 v = ((const float4*)src)[i];
    ((uint2*)h)[i] = make_uint2(pack_h2(v.x, v.y), pack_h2(v.z, v.w));
}
__global__ void init_kernel(const float* __restrict__ w1, const float* __restrict__ w2) {
    int i = blockIdx.x * 256 + threadIdx.x;
    if (i == 0) g_arrive = 0;
    if (i < WSZ) {
        float a = w1[i], b = w2[i];
        g_W1[i] = a; g_W2[i] = b;
        g_S1[i] = 0.f; g_S2[i] = 0.f;
        __half ha = __float2half_rn(a);
        g_W1h[i] = ha; g_W1l[i] = __float2half_rn(a - __half2float(ha));
        __half hb = __float2half_rn(b);
        g_W2hA[i] = hb; g_W2l[i] = __float2half_rn(b - __half2float(hb));
    }
}

// ---------------- launcher ----------------------------------------------------
extern "C" void kernel_launch(void* const* d_in, const int* in_sizes, int n_in,
                              void* d_out, int out_size)
{
    const float* x       = (const float*)d_in[0];
    const float* w_q     = (const float*)d_in[1];
    const float* w_k     = (const float*)d_in[2];
    const float* w_v     = (const float*)d_in[3];
    const float* mem_w1  = (const float*)d_in[4];
    const float* mem_w2  = (const float*)d_in[5];
    const float* alpha_t = (const float*)d_in[6];
    const float* lr_t    = (const float*)d_in[7];
    const float* decay_t = (const float*)d_in[8];
    const int*   upd     = (const int*)d_in[9];
    float* out = (float*)d_out;

    __half *xh, *xl, *wqh, *wql, *wkh, *wvh;
    cudaGetSymbolAddress((void**)&xh,  g_xh);
    cudaGetSymbolAddress((void**)&xl,  g_xl);
    cudaGetSymbolAddress((void**)&wqh, g_wqh);
    cudaGetSymbolAddress((void**)&wql, g_wql);
    cudaGetSymbolAddress((void**)&wkh, g_wkh);
    cudaGetSymbolAddress((void**)&wvh, g_wvh);

    cudaFuncSetAttribute(qkv_kernel, cudaFuncAttributeMaxDynamicSharedMemorySize, P_SMEM);
    cudaFuncSetAttribute(ro1_kernel, cudaFuncAttributeMaxDynamicSharedMemorySize, P_SMEM);
    cudaFuncSetAttribute(ro2_kernel, cudaFuncAttributeMaxDynamicSharedMemorySize, P_SMEM);
    cudaFuncSetAttribute(chunk_loop, cudaFuncAttributeMaxDynamicSharedMemorySize, P_SMEM);

    const dim3 thr(256);

    {
        int n4 = ROWS_TOTAL * D_IN / 4;
        split_kernel<<<(n4 + 255) / 256, thr>>>(x, xh, xl, n4);
        int w4 = D_IN * D_IN / 4;
        split_kernel<<<(w4 + 255) / 256, thr>>>(w_q, wqh, wql, w4);
        half_kernel<<<(w4 + 255) / 256, thr>>>(w_k, wkh, w4);
        half_kernel<<<(w4 + 255) / 256, thr>>>(w_v, wvh, w4);
    }
    init_kernel<<<WSZ / 256, thr>>>(mem_w1, mem_w2);

    qkv_kernel<<<dim3(D_IN / 128, ROWS_TOTAL / 64, 3), thr, P_SMEM>>>();

    chunk_loop<<<NB, thr, P_SMEM>>>(alpha_t, lr_t, decay_t, upd);

    ro1_kernel<<<dim3(HID / 128, ROWS_TOTAL / 64), thr, P_SMEM>>>();
    ro2_kernel<<<dim3(D_IN / 128, ROWS_TOTAL / 64), thr, P_SMEM>>>(out);

    (void)in_sizes; (void)n_in; (void)out_size;
}

// round 7
// speedup vs baseline: 5.9727x; 1.3142x over previous
#include <cuda_runtime.h>
#include <cuda_fp16.h>
#include <cstdint>
#include <math.h>

// ---------------- problem constants ----------------------------------------
#define D_IN   512
#define HID    1024
#define SEQ    4096
#define BATCH  4
#define CHUNK  256
#define NCHUNK 16
#define ROWS_TOTAL (BATCH*SEQ)     // 16384
#define ROWS_CHUNK (BATCH*CHUNK)   // 1024
#define WSZ    (D_IN*HID)          // 524288
#define NB     148

// ---------------- scratch (device globals) ----------------------------------
__device__ float g_V [ROWS_TOTAL*D_IN];   // chunk-major f32
__device__ float g_H [ROWS_CHUNK*HID];    // pre-gelu f32
__device__ float g_W1[WSZ], g_W2[WSZ], g_S1[WSZ], g_S2[WSZ];
__device__ unsigned g_arrive;

__device__ __half g_xh [ROWS_TOTAL*D_IN];
__device__ __half g_Qh [ROWS_TOTAL*D_IN];
__device__ __half g_Kh [ROWS_TOTAL*D_IN];        // chunk-major
__device__ __half g_W1h[WSZ];
__device__ __half g_W2hA[WSZ], g_W2hB[WSZ];      // hi ping-pong
__device__ __half g_Ah [ROWS_CHUNK*HID];
__device__ __half g_Eh [ROWS_CHUNK*D_IN];
__device__ __half g_dHh[ROWS_CHUNK*HID];
__device__ __half g_Hqh[ROWS_TOTAL*HID];
__device__ __half g_wqh[D_IN*D_IN], g_wkh[D_IN*D_IN], g_wvh[D_IN*D_IN];

// ---------------- math helpers ----------------------------------------------
__device__ __forceinline__ float gelu_f(float x) {
    return 0.5f * x * (1.0f + erff(x * 0.70710678118654752f));
}
__device__ __forceinline__ float gelu_grad_f(float x) {
    float cdf = 0.5f * (1.0f + erff(x * 0.70710678118654752f));
    float pdf = 0.3989422804014327f * __expf(-0.5f * x * x);
    return cdf + x * pdf;
}
__device__ __forceinline__ float sigmoid_f(float x) {
    return 1.0f / (1.0f + __expf(-x));
}
__device__ __forceinline__ uint32_t pack_h2(float v0, float v1) {
    __half2 hh = __floats2half2_rn(v0, v1);
    return *(uint32_t*)&hh;
}

// ---------------- PTX helpers ------------------------------------------------
__device__ __forceinline__ uint32_t smem_u32(const void* p) {
    uint32_t a;
    asm("{ .reg .u64 t; cvta.to.shared.u64 t, %1; cvt.u32.u64 %0, t; }" : "=r"(a) : "l"(p));
    return a;
}
__device__ __forceinline__ void cp16(uint32_t d, const void* s) {
    asm volatile("cp.async.cg.shared.global [%0], [%1], 16;" :: "r"(d), "l"(s));
}
__device__ __forceinline__ void ldsm4(uint32_t a, uint32_t& r0, uint32_t& r1,
                                      uint32_t& r2, uint32_t& r3) {
    asm volatile("ldmatrix.sync.aligned.m8n8.x4.shared.b16 {%0,%1,%2,%3}, [%4];"
                 : "=r"(r0), "=r"(r1), "=r"(r2), "=r"(r3) : "r"(a));
}
__device__ __forceinline__ void ldsm4t(uint32_t a, uint32_t& r0, uint32_t& r1,
                                       uint32_t& r2, uint32_t& r3) {
    asm volatile("ldmatrix.sync.aligned.m8n8.x4.trans.shared.b16 {%0,%1,%2,%3}, [%4];"
                 : "=r"(r0), "=r"(r1), "=r"(r2), "=r"(r3) : "r"(a));
}
__device__ __forceinline__ void mma16816(float* c, const uint32_t* a, const uint32_t* b) {
    asm volatile(
        "mma.sync.aligned.m16n8k16.row.col.f32.f16.f16.f32 "
        "{%0,%1,%2,%3}, {%4,%5,%6,%7}, {%8,%9}, {%0,%1,%2,%3};"
        : "+f"(c[0]), "+f"(c[1]), "+f"(c[2]), "+f"(c[3])
        : "r"(a[0]), "r"(a[1]), "r"(a[2]), "r"(a[3]), "r"(b[0]), "r"(b[1]));
}

#define P_SMEM 36864   // 3 stages * (A 4KB + B 8KB)

// ============================================================================
// 1-term fp16 tile GEMM, 3-stage cp.async pipeline. Tile BM x 128, BK=32,
// 8 warps (2m x 4n), warp tile (BM/2) x 32.
// EPI: 0 C=v f32 | 1 Ch=h(v) | 3 C=v f32, Ch=h(gelu(v)) | 4 Ch=h((v-aux)*scale)
//      5 Ch=h(v*gelu'(aux)) | 6 momentum: s=decay*S-lr*v; S=s; w=om*C+s; C=w; Ch=h(w)
//      7 perm, Ch=h(v) | 8 perm, C=v f32 | 9 Ch=h(gelu(v))
// ============================================================================
template<int BM, bool TA, bool TB, int EPI>
__device__ __forceinline__ void tile_gemm(
    const __half* __restrict__ A_, int lda,
    const __half* __restrict__ B_, int ldb,
    int K, int m0, int n0, uint32_t sbase,
    float* __restrict__ C, __half* __restrict__ Ch, int ldc,
    const float* __restrict__ aux, float scale,
    float decay, float lr, float om, float* __restrict__ S)
{
    constexpr int A_T = BM * 64;
    constexpr int B_T = 8192;
    constexpr int BUF = A_T + B_T;
    constexpr int MT  = BM / 32;

    const int tid = threadIdx.x, wid = tid >> 5, lane = tid & 31;
    const int wm = (wid & 1) * (BM / 2);
    const int wn = (wid >> 1) * 32;

    float acc[MT][4][4];
    #pragma unroll
    for (int a = 0; a < MT; a++)
        #pragma unroll
        for (int b = 0; b < 4; b++)
            #pragma unroll
            for (int d = 0; d < 4; d++) acc[a][b][d] = 0.f;

    // ---- A staging (one 16B cp per active thread) ----
    const __half* srcA = nullptr;
    uint32_t dA = 0;
    bool aAct = true;
    if (!TA) {
        if (BM == 64) {
            int r = tid >> 2, kq = tid & 3;
            srcA = A_ + (size_t)(m0 + r) * lda + kq * 8;
            dA = r * 64 + ((kq ^ ((r >> 1) & 3)) << 4);
        } else {
            aAct = tid < 128;
            int r = (tid & 127) >> 2, kq = tid & 3;
            srcA = A_ + (aAct ? ((size_t)(m0 + r) * lda + kq * 8) : 0);
            dA = aAct ? (uint32_t)(r * 64 + ((kq ^ ((r >> 1) & 3)) << 4)) : 0u;
        }
    } else {
        if (BM == 64) {
            int kr = tid >> 3, rq = tid & 7;
            srcA = A_ + (size_t)kr * lda + m0 + rq * 8;
            dA = kr * 128 + ((rq ^ (kr & 7)) << 4);
        } else {
            aAct = tid < 128;
            int kr = (tid & 127) >> 2, rq = tid & 3;
            srcA = A_ + (aAct ? ((size_t)kr * lda + m0 + rq * 8) : 0);
            dA = aAct ? (uint32_t)(kr * 64 + ((rq ^ (kr & 3)) << 4)) : 0u;
        }
    }
    const size_t advA = TA ? (size_t)32 * lda : 32;

    // ---- B staging (two 16B cp per thread) ----
    const __half* srcB[2];
    uint32_t dB[2];
    #pragma unroll
    for (int i = 0; i < 2; i++) {
        int fi = tid + i * 256;
        if (!TB) {
            int kr = fi >> 4, rq = fi & 15;
            srcB[i] = B_ + (size_t)kr * ldb + n0 + rq * 8;
            dB[i] = A_T + kr * 256 + ((rq ^ (kr & 7)) << 4);
        } else {
            int r = fi >> 2, kq = fi & 3;
            srcB[i] = B_ + (size_t)(n0 + r) * ldb + kq * 8;
            dB[i] = A_T + r * 64 + ((kq ^ ((r >> 1) & 3)) << 4);
        }
    }
    const size_t advB = TB ? 32 : (size_t)32 * ldb;

    // ---- ldmatrix addresses (relative to buffer base) ----
    uint32_t aA[2][MT], aB[2][2];
    #pragma unroll
    for (int s = 0; s < 2; s++) {
        #pragma unroll
        for (int mt = 0; mt < MT; mt++) {
            if (!TA) {
                int r = wm + mt * 16 + (lane & 15);
                int g = 2 * s + (lane >> 4);
                aA[s][mt] = r * 64 + ((g ^ ((r >> 1) & 3)) << 4);
            } else {
                int k = 16 * s + (lane & 7) + (lane >> 4) * 8;
                int mg = ((wm + mt * 16) >> 3) + ((lane >> 3) & 1);
                aA[s][mt] = (BM == 64) ? k * 128 + ((mg ^ (k & 7)) << 4)
                                       : k * 64  + ((mg ^ (k & 3)) << 4);
            }
        }
        #pragma unroll
        for (int j = 0; j < 2; j++) {
            if (!TB) {
                int k = 16 * s + (lane & 7) + ((lane >> 3) & 1) * 8;
                int ng = ((wn + j * 16) >> 3) + (lane >> 4);
                aB[s][j] = A_T + k * 256 + ((ng ^ (k & 7)) << 4);
            } else {
                int n = wn + j * 16 + (lane & 7) + (lane >> 4) * 8;
                int g = 2 * s + ((lane >> 3) & 1);
                aB[s][j] = A_T + n * 64 + ((g ^ ((n >> 1) & 3)) << 4);
            }
        }
    }

    const int NC = K >> 5;

    auto issue = [&](int c, int buf) {
        uint32_t b = sbase + buf * BUF;
        if (aAct) cp16(b + dA, srcA + c * advA);
        cp16(b + dB[0], srcB[0] + c * advB);
        cp16(b + dB[1], srcB[1] + c * advB);
        asm volatile("cp.async.commit_group;");
    };

    issue(0, 0);
    issue(1, 1);
    for (int c = 0; c < NC; c++) {
        if (c < NC - 1) asm volatile("cp.async.wait_group 1;");
        else            asm volatile("cp.async.wait_group 0;");
        __syncthreads();
        if (c + 2 < NC) issue(c + 2, (c + 2) % 3);

        const uint32_t bb = sbase + (c % 3) * BUF;
        uint32_t FA[2][MT][4], FB[2][4][2];
        #pragma unroll
        for (int s = 0; s < 2; s++) {
            #pragma unroll
            for (int mt = 0; mt < MT; mt++) {
                if (!TA) ldsm4 (bb + aA[s][mt], FA[s][mt][0], FA[s][mt][1], FA[s][mt][2], FA[s][mt][3]);
                else     ldsm4t(bb + aA[s][mt], FA[s][mt][0], FA[s][mt][1], FA[s][mt][2], FA[s][mt][3]);
            }
            #pragma unroll
            for (int j = 0; j < 2; j++) {
                if (!TB) ldsm4t(bb + aB[s][j], FB[s][2*j][0], FB[s][2*j][1], FB[s][2*j+1][0], FB[s][2*j+1][1]);
                else     ldsm4 (bb + aB[s][j], FB[s][2*j][0], FB[s][2*j][1], FB[s][2*j+1][0], FB[s][2*j+1][1]);
            }
        }
        #pragma unroll
        for (int s = 0; s < 2; s++)
            #pragma unroll
            for (int mt = 0; mt < MT; mt++)
                #pragma unroll
                for (int nt = 0; nt < 4; nt++)
                    mma16816(acc[mt][nt], FA[s][mt], FB[s][nt]);
    }
    __syncthreads();   // protect smem reuse by the caller's next tile

    // ---- epilogue ----
    #pragma unroll
    for (int mt = 0; mt < MT; mt++) {
        #pragma unroll
        for (int half = 0; half < 2; half++) {
            int r = m0 + wm + mt * 16 + (lane >> 2) + half * 8;
            #pragma unroll
            for (int nt = 0; nt < 4; nt++) {
                int cc = n0 + wn + nt * 8 + 2 * (lane & 3);
                float v0 = acc[mt][nt][half * 2 + 0];
                float v1 = acc[mt][nt][half * 2 + 1];
                size_t idx = (size_t)r * ldc + cc;
                if (EPI == 0) {
                    *(float2*)(C + idx) = make_float2(v0, v1);
                } else if (EPI == 1) {
                    *(uint32_t*)(Ch + idx) = pack_h2(v0, v1);
                } else if (EPI == 3) {
                    *(float2*)(C + idx) = make_float2(v0, v1);
                    *(uint32_t*)(Ch + idx) = pack_h2(gelu_f(v0), gelu_f(v1));
                } else if (EPI == 4) {
                    float2 a2 = *(const float2*)(aux + idx);
                    *(uint32_t*)(Ch + idx) = pack_h2((v0 - a2.x) * scale, (v1 - a2.y) * scale);
                } else if (EPI == 5) {
                    float2 a2 = *(const float2*)(aux + idx);
                    *(uint32_t*)(Ch + idx) = pack_h2(v0 * gelu_grad_f(a2.x), v1 * gelu_grad_f(a2.y));
                } else if (EPI == 6) {
                    float2 w = *(const float2*)(C + idx);
                    float2 s = *(const float2*)(S + idx);
                    float s0 = decay * s.x - lr * v0;
                    float s1 = decay * s.y - lr * v1;
                    float w0 = om * w.x + s0, w1 = om * w.y + s1;
                    *(float2*)(S + idx) = make_float2(s0, s1);
                    *(float2*)(C + idx) = make_float2(w0, w1);
                    *(uint32_t*)(Ch + idx) = pack_h2(w0, w1);
                } else if (EPI == 7) {
                    int b = r >> 12, sq = r & 4095, chn = sq >> 8, t = sq & 255;
                    size_t orow = (size_t)(chn * 1024 + b * 256 + t) * ldc + cc;
                    *(uint32_t*)(Ch + orow) = pack_h2(v0, v1);
                } else if (EPI == 8) {
                    int b = r >> 12, sq = r & 4095, chn = sq >> 8, t = sq & 255;
                    size_t orow = (size_t)(chn * 1024 + b * 256 + t) * ldc + cc;
                    *(float2*)(C + orow) = make_float2(v0, v1);
                } else { // EPI == 9
                    *(uint32_t*)(Ch + idx) = pack_h2(gelu_f(v0), gelu_f(v1));
                }
            }
        }
    }
}

// ---------------- standalone wrappers ---------------------------------------
__global__ void __launch_bounds__(256) qkv_kernel() {
    extern __shared__ char smem[];
    const uint32_t sbase = smem_u32(smem);
    int m0 = blockIdx.y * 64, n0 = blockIdx.x * 128;
    int z = blockIdx.z;
    if (z == 0)
        tile_gemm<64,false,false,1>(g_xh, D_IN, g_wqh, D_IN, D_IN,
            m0, n0, sbase, nullptr, g_Qh, D_IN, nullptr, 0.f, 0.f, 0.f, 0.f, nullptr);
    else if (z == 1)
        tile_gemm<64,false,false,7>(g_xh, D_IN, g_wkh, D_IN, D_IN,
            m0, n0, sbase, nullptr, g_Kh, D_IN, nullptr, 0.f, 0.f, 0.f, 0.f, nullptr);
    else
        tile_gemm<64,false,false,8>(g_xh, D_IN, g_wvh, D_IN, D_IN,
            m0, n0, sbase, g_V, nullptr, D_IN, nullptr, 0.f, 0.f, 0.f, 0.f, nullptr);
}

__global__ void __launch_bounds__(256) ro1_kernel() {
    extern __shared__ char smem[];
    const uint32_t sbase = smem_u32(smem);
    tile_gemm<64,false,false,9>(g_Qh, D_IN, g_W1h, HID, D_IN,
        blockIdx.y * 64, blockIdx.x * 128, sbase,
        nullptr, g_Hqh, HID, nullptr, 0.f, 0.f, 0.f, 0.f, nullptr);
}

__global__ void __launch_bounds__(256) ro2_kernel(float* __restrict__ out) {
    extern __shared__ char smem[];
    const uint32_t sbase = smem_u32(smem);
    tile_gemm<64,false,false,0>(g_Hqh, HID, g_W2hA, D_IN, HID,
        blockIdx.y * 64, blockIdx.x * 128, sbase,
        out, nullptr, D_IN, nullptr, 0.f, 0.f, 0.f, 0.f, nullptr);
}

// ---------------- software grid barrier --------------------------------------
__device__ __forceinline__ void gsync(unsigned& epoch) {
    __syncthreads();
    if (threadIdx.x == 0) {
        __threadfence();
        epoch++;
        atomicAdd(&g_arrive, 1u);
        const unsigned target = epoch * NB;
        while (__ldcg(&g_arrive) < target) __nanosleep(32);
        __threadfence();
    }
    __syncthreads();
}

// ---------------- persistent chunk loop --------------------------------------
__global__ void __launch_bounds__(256, 1)
chunk_loop(const float* __restrict__ alpha_t, const float* __restrict__ lr_t,
           const float* __restrict__ decay_t, const int* __restrict__ upd)
{
    if (*upd == 0) return;
    const float alpha = sigmoid_f(*alpha_t);
    const float lr    = sigmoid_f(*lr_t);
    const float decay = sigmoid_f(*decay_t);
    const float om    = 1.0f - alpha;
    const float escale = 2.0f / (float)(ROWS_CHUNK * D_IN);

    extern __shared__ char smem[];
    const uint32_t sbase = smem_u32(smem);
    unsigned epoch = 0;

    for (int c = 0; c < NCHUNK; c++) {
        const __half* Kch = g_Kh + (size_t)c * ROWS_CHUNK * D_IN;
        const float*  Vc  = g_V  + (size_t)c * ROWS_CHUNK * D_IN;
        __half* W2cur = (c & 1) ? g_W2hB : g_W2hA;
        __half* W2nxt = (c & 1) ? g_W2hA : g_W2hB;

        // P1: H = Kc @ W1 (f32), Ah = h(gelu(H))      128 tiles BM=64 K=512
        for (int t = blockIdx.x; t < 128; t += NB)
            tile_gemm<64,false,false,3>(Kch, D_IN, g_W1h, HID, D_IN,
                (t >> 3) * 64, (t & 7) * 128, sbase,
                g_H, g_Ah, HID, nullptr, 0.f, 0.f, 0.f, 0.f, nullptr);
        gsync(epoch);

        // P2: Eh = h((A @ W2 - Vc)*escale)            128 tiles BM=32 K=1024
        for (int t = blockIdx.x; t < 128; t += NB)
            tile_gemm<32,false,false,4>(g_Ah, HID, W2cur, D_IN, HID,
                (t >> 2) * 32, (t & 3) * 128, sbase,
                nullptr, g_Eh, D_IN, Vc, escale, 0.f, 0.f, 0.f, nullptr);
        gsync(epoch);

        // P3: dHh = h((E @ W2^T)*gelu'(H))            128 tiles BM=64 K=512
        //     G2 = A^T @ E, fused W2/S2 update -> W2nxt  128 tiles BM=32 K=1024
        for (int t = blockIdx.x; t < 256; t += NB) {
            if (t < 128)
                tile_gemm<64,false,true,5>(g_Eh, D_IN, W2cur, D_IN, D_IN,
                    (t >> 3) * 64, (t & 7) * 128, sbase,
                    nullptr, g_dHh, HID, g_H, 0.f, 0.f, 0.f, 0.f, nullptr);
            else {
                int u = t - 128;
                tile_gemm<32,true,false,6>(g_Ah, HID, g_Eh, D_IN, ROWS_CHUNK,
                    (u >> 2) * 32, (u & 3) * 128, sbase,
                    g_W2, W2nxt, D_IN, nullptr, 0.f, decay, lr, om, g_S2);
            }
        }
        gsync(epoch);

        // P4: G1 = Kc^T @ dH, fused W1/S1 update      128 tiles BM=32 K=1024
        for (int t = blockIdx.x; t < 128; t += NB)
            tile_gemm<32,true,false,6>(Kch, D_IN, g_dHh, HID, ROWS_CHUNK,
                (t >> 3) * 32, (t & 7) * 128, sbase,
                g_W1, g_W1h, HID, nullptr, 0.f, decay, lr, om, g_S1);
        gsync(epoch);
    }
}

// ---------------- init / convert kernels -------------------------------------
__global__ void half_kernel(const float* __restrict__ src, __half* __restrict__ h, int n4) {
    int i = blockIdx.x * 256 + threadIdx.x;
    if (i >= n4) return;
    float4 v = ((const float4*)src)[i];
    ((uint2*)h)[i] = make_uint2(pack_h2(v.x, v.y), pack_h2(v.z, v.w));
}
__global__ void init_kernel(const float* __restrict__ w1, const float* __restrict__ w2) {
    int i = blockIdx.x * 256 + threadIdx.x;
    if (i == 0) g_arrive = 0;
    if (i < WSZ) {
        float a = w1[i], b = w2[i];
        g_W1[i] = a; g_W2[i] = b;
        g_S1[i] = 0.f; g_S2[i] = 0.f;
        g_W1h[i]  = __float2half_rn(a);
        g_W2hA[i] = __float2half_rn(b);
    }
}

// ---------------- launcher ----------------------------------------------------
extern "C" void kernel_launch(void* const* d_in, const int* in_sizes, int n_in,
                              void* d_out, int out_size)
{
    const float* x       = (const float*)d_in[0];
    const float* w_q     = (const float*)d_in[1];
    const float* w_k     = (const float*)d_in[2];
    const float* w_v     = (const float*)d_in[3];
    const float* mem_w1  = (const float*)d_in[4];
    const float* mem_w2  = (const float*)d_in[5];
    const float* alpha_t = (const float*)d_in[6];
    const float* lr_t    = (const float*)d_in[7];
    const float* decay_t = (const float*)d_in[8];
    const int*   upd     = (const int*)d_in[9];
    float* out = (float*)d_out;

    __half *xh, *wqh, *wkh, *wvh;
    cudaGetSymbolAddress((void**)&xh,  g_xh);
    cudaGetSymbolAddress((void**)&wqh, g_wqh);
    cudaGetSymbolAddress((void**)&wkh, g_wkh);
    cudaGetSymbolAddress((void**)&wvh, g_wvh);

    cudaFuncSetAttribute(qkv_kernel, cudaFuncAttributeMaxDynamicSharedMemorySize, P_SMEM);
    cudaFuncSetAttribute(ro1_kernel, cudaFuncAttributeMaxDynamicSharedMemorySize, P_SMEM);
    cudaFuncSetAttribute(ro2_kernel, cudaFuncAttributeMaxDynamicSharedMemorySize, P_SMEM);
    cudaFuncSetAttribute(chunk_loop, cudaFuncAttributeMaxDynamicSharedMemorySize, P_SMEM);

    const dim3 thr(256);

    {
        int n4 = ROWS_TOTAL * D_IN / 4;
        half_kernel<<<(n4 + 255) / 256, thr>>>(x, xh, n4);
        int w4 = D_IN * D_IN / 4;
        half_kernel<<<(w4 + 255) / 256, thr>>>(w_q, wqh, w4);
        half_kernel<<<(w4 + 255) / 256, thr>>>(w_k, wkh, w4);
        half_kernel<<<(w4 + 255) / 256, thr>>>(w_v, wvh, w4);
    }
    init_kernel<<<WSZ / 256, thr>>>(mem_w1, mem_w2);

    qkv_kernel<<<dim3(D_IN / 128, ROWS_TOTAL / 64, 3), thr, P_SMEM>>>();

    chunk_loop<<<NB, thr, P_SMEM>>>(alpha_t, lr_t, decay_t, upd);

    ro1_kernel<<<dim3(HID / 128, ROWS_TOTAL / 64), thr, P_SMEM>>>();
    ro2_kernel<<<dim3(D_IN / 128, ROWS_TOTAL / 64), thr, P_SMEM>>>(out);

    (void)in_sizes; (void)n_in; (void)out_size;
}

// round 8
// speedup vs baseline: 6.5763x; 1.1011x over previous
#include <cuda_runtime.h>
#include <cuda_fp16.h>
#include <cstdint>
#include <math.h>

// ---------------- problem constants ----------------------------------------
#define D_IN   512
#define HID    1024
#define SEQ    4096
#define BATCH  4
#define CHUNK  256
#define NCHUNK 16
#define ROWS_TOTAL (BATCH*SEQ)     // 16384
#define ROWS_CHUNK (BATCH*CHUNK)   // 1024
#define WSZ    (D_IN*HID)          // 524288
#define NB     148

// ---------------- scratch (device globals) ----------------------------------
__device__ float g_V [ROWS_TOTAL*D_IN];   // chunk-major f32
__device__ float g_H [ROWS_CHUNK*HID];    // pre-gelu f32
__device__ float g_W1[WSZ], g_W2[WSZ], g_S1[WSZ], g_S2[WSZ];
__device__ unsigned g_arrive;

__device__ __half g_xh [ROWS_TOTAL*D_IN];
__device__ __half g_Qh [ROWS_TOTAL*D_IN];
__device__ __half g_Kh [ROWS_TOTAL*D_IN];        // chunk-major
__device__ __half g_W1h[WSZ];
__device__ __half g_W2hA[WSZ], g_W2hB[WSZ];      // hi ping-pong
__device__ __half g_Ah [ROWS_CHUNK*HID];
__device__ __half g_Eh [ROWS_CHUNK*D_IN];
__device__ __half g_dHh[ROWS_CHUNK*HID];
__device__ __half g_Hqh[ROWS_TOTAL*HID];
__device__ __half g_wqh[D_IN*D_IN], g_wkh[D_IN*D_IN], g_wvh[D_IN*D_IN];

// ---------------- math helpers ----------------------------------------------
__device__ __forceinline__ float gelu_f(float x) {
    return 0.5f * x * (1.0f + erff(x * 0.70710678118654752f));
}
__device__ __forceinline__ float gelu_grad_f(float x) {
    float cdf = 0.5f * (1.0f + erff(x * 0.70710678118654752f));
    float pdf = 0.3989422804014327f * __expf(-0.5f * x * x);
    return cdf + x * pdf;
}
__device__ __forceinline__ float sigmoid_f(float x) {
    return 1.0f / (1.0f + __expf(-x));
}
__device__ __forceinline__ uint32_t pack_h2(float v0, float v1) {
    __half2 hh = __floats2half2_rn(v0, v1);
    return *(uint32_t*)&hh;
}

// ---------------- PTX helpers ------------------------------------------------
__device__ __forceinline__ uint32_t smem_u32(const void* p) {
    uint32_t a;
    asm("{ .reg .u64 t; cvta.to.shared.u64 t, %1; cvt.u32.u64 %0, t; }" : "=r"(a) : "l"(p));
    return a;
}
__device__ __forceinline__ void cp16(uint32_t d, const void* s) {
    asm volatile("cp.async.cg.shared.global [%0], [%1], 16;" :: "r"(d), "l"(s));
}
__device__ __forceinline__ void ldsm4(uint32_t a, uint32_t& r0, uint32_t& r1,
                                      uint32_t& r2, uint32_t& r3) {
    asm volatile("ldmatrix.sync.aligned.m8n8.x4.shared.b16 {%0,%1,%2,%3}, [%4];"
                 : "=r"(r0), "=r"(r1), "=r"(r2), "=r"(r3) : "r"(a));
}
__device__ __forceinline__ void ldsm4t(uint32_t a, uint32_t& r0, uint32_t& r1,
                                       uint32_t& r2, uint32_t& r3) {
    asm volatile("ldmatrix.sync.aligned.m8n8.x4.trans.shared.b16 {%0,%1,%2,%3}, [%4];"
                 : "=r"(r0), "=r"(r1), "=r"(r2), "=r"(r3) : "r"(a));
}
__device__ __forceinline__ void mma16816(float* c, const uint32_t* a, const uint32_t* b) {
    asm volatile(
        "mma.sync.aligned.m16n8k16.row.col.f32.f16.f16.f32 "
        "{%0,%1,%2,%3}, {%4,%5,%6,%7}, {%8,%9}, {%0,%1,%2,%3};"
        : "+f"(c[0]), "+f"(c[1]), "+f"(c[2]), "+f"(c[3])
        : "r"(a[0]), "r"(a[1]), "r"(a[2]), "r"(a[3]), "r"(b[0]), "r"(b[1]));
}

#define P_SMEM 73728   // 3 stages * (A 8KB + B 16KB), BK=64, BM=64 case

// ============================================================================
// 1-term fp16 tile GEMM, BK=64, 3-stage cp.async pipeline. Tile BM x 128,
// 8 warps (2m x 4n), warp tile (BM/2) x 32.
// EPI: 0 C=v f32 | 1 Ch=h(v) | 3 C=v f32, Ch=h(gelu(v)) | 4 Ch=h((v-aux)*scale)
//      5 Ch=h(v*gelu'(aux)) | 6 momentum: s=decay*S-lr*v; S=s; w=om*C+s; C=w; Ch=h(w)
//      7 perm, Ch=h(v) | 8 perm, C=v f32 | 9 Ch=h(gelu(v))
// ============================================================================
template<int BM, bool TA, bool TB, int EPI>
__device__ __forceinline__ void tile_gemm(
    const __half* __restrict__ A_, int lda,
    const __half* __restrict__ B_, int ldb,
    int K, int m0, int n0, uint32_t sbase,
    float* __restrict__ C, __half* __restrict__ Ch, int ldc,
    const float* __restrict__ aux, float scale,
    float decay, float lr, float om, float* __restrict__ S)
{
    constexpr int A_T = BM * 128;        // BM x 64 halfs
    constexpr int B_T = 16384;           // 128 x 64 halfs
    constexpr int BUF = A_T + B_T;
    constexpr int MT  = BM / 32;
    constexpr int ACP = (BM == 64) ? 2 : 1;   // A cp16 per thread

    const int tid = threadIdx.x, wid = tid >> 5, lane = tid & 31;
    const int wm = (wid & 1) * (BM / 2);
    const int wn = (wid >> 1) * 32;

    float acc[MT][4][4];
    #pragma unroll
    for (int a = 0; a < MT; a++)
        #pragma unroll
        for (int b = 0; b < 4; b++)
            #pragma unroll
            for (int d = 0; d < 4; d++) acc[a][b][d] = 0.f;

    // ---- A staging ----
    const __half* srcA[ACP];
    uint32_t dA[ACP];
    #pragma unroll
    for (int i = 0; i < ACP; i++) {
        int idx = tid + i * 256;
        if (!TA) {
            int r = idx >> 3, kq = idx & 7;                  // BM rows x 8 groups
            srcA[i] = A_ + (size_t)(m0 + r) * lda + kq * 8;
            dA[i] = r * 128 + ((kq ^ (r & 7)) << 4);
        } else {
            if (BM == 64) {
                int kr = idx >> 3, rq = idx & 7;             // 64 k-rows x 8 groups
                srcA[i] = A_ + (size_t)kr * lda + m0 + rq * 8;
                dA[i] = kr * 128 + ((rq ^ (kr & 7)) << 4);
            } else {
                int kr = idx >> 2, rq = idx & 3;             // 64 k-rows x 4 groups
                srcA[i] = A_ + (size_t)kr * lda + m0 + rq * 8;
                dA[i] = kr * 64 + ((rq ^ (kr & 3)) << 4);
            }
        }
    }
    const size_t advA = TA ? (size_t)64 * lda : 64;

    // ---- B staging (4 cp16 per thread) ----
    const __half* srcB[4];
    uint32_t dB[4];
    #pragma unroll
    for (int i = 0; i < 4; i++) {
        int fi = tid + i * 256;
        if (!TB) {
            int kr = fi >> 4, rq = fi & 15;                  // 64 k-rows x 16 groups
            srcB[i] = B_ + (size_t)kr * ldb + n0 + rq * 8;
            dB[i] = A_T + kr * 256 + ((rq ^ (kr & 7)) << 4);
        } else {
            int r = fi >> 3, kq = fi & 7;                    // 128 n-rows x 8 groups
            srcB[i] = B_ + (size_t)(n0 + r) * ldb + kq * 8;
            dB[i] = A_T + r * 128 + ((kq ^ (r & 7)) << 4);
        }
    }
    const size_t advB = TB ? 64 : (size_t)64 * ldb;

    // ---- ldmatrix addresses (s = 0..3 k16-steps within BK=64) ----
    uint32_t aA[4][MT], aB[4][2];
    #pragma unroll
    for (int s = 0; s < 4; s++) {
        #pragma unroll
        for (int mt = 0; mt < MT; mt++) {
            if (!TA) {
                int r = wm + mt * 16 + (lane & 15);
                int g = 2 * s + (lane >> 4);
                aA[s][mt] = r * 128 + ((g ^ (r & 7)) << 4);
            } else {
                int k = 16 * s + (lane & 7) + (lane >> 4) * 8;
                int mg = ((wm + mt * 16) >> 3) + ((lane >> 3) & 1);
                aA[s][mt] = (BM == 64) ? k * 128 + ((mg ^ (k & 7)) << 4)
                                       : k * 64  + ((mg ^ (k & 3)) << 4);
            }
        }
        #pragma unroll
        for (int j = 0; j < 2; j++) {
            if (!TB) {
                int k = 16 * s + (lane & 7) + ((lane >> 3) & 1) * 8;
                int ng = ((wn + j * 16) >> 3) + (lane >> 4);
                aB[s][j] = A_T + k * 256 + ((ng ^ (k & 7)) << 4);
            } else {
                int n = wn + j * 16 + (lane & 7) + (lane >> 4) * 8;
                int g = 2 * s + ((lane >> 3) & 1);
                aB[s][j] = A_T + n * 128 + ((g ^ (n & 7)) << 4);
            }
        }
    }

    const int NC = K >> 6;

    auto issue = [&](int c, int buf) {
        uint32_t b = sbase + buf * BUF;
        #pragma unroll
        for (int i = 0; i < ACP; i++) cp16(b + dA[i], srcA[i] + c * advA);
        #pragma unroll
        for (int i = 0; i < 4;   i++) cp16(b + dB[i], srcB[i] + c * advB);
        asm volatile("cp.async.commit_group;");
    };

    issue(0, 0);
    issue(1, 1);
    for (int c = 0; c < NC; c++) {
        if (c < NC - 1) asm volatile("cp.async.wait_group 1;");
        else            asm volatile("cp.async.wait_group 0;");
        __syncthreads();
        if (c + 2 < NC) issue(c + 2, (c + 2) % 3);

        const uint32_t bb = sbase + (c % 3) * BUF;
        uint32_t FA[4][MT][4], FB[4][4][2];
        #pragma unroll
        for (int s = 0; s < 4; s++) {
            #pragma unroll
            for (int mt = 0; mt < MT; mt++) {
                if (!TA) ldsm4 (bb + aA[s][mt], FA[s][mt][0], FA[s][mt][1], FA[s][mt][2], FA[s][mt][3]);
                else     ldsm4t(bb + aA[s][mt], FA[s][mt][0], FA[s][mt][1], FA[s][mt][2], FA[s][mt][3]);
            }
            #pragma unroll
            for (int j = 0; j < 2; j++) {
                if (!TB) ldsm4t(bb + aB[s][j], FB[s][2*j][0], FB[s][2*j][1], FB[s][2*j+1][0], FB[s][2*j+1][1]);
                else     ldsm4 (bb + aB[s][j], FB[s][2*j][0], FB[s][2*j][1], FB[s][2*j+1][0], FB[s][2*j+1][1]);
            }
        }
        #pragma unroll
        for (int s = 0; s < 4; s++)
            #pragma unroll
            for (int mt = 0; mt < MT; mt++)
                #pragma unroll
                for (int nt = 0; nt < 4; nt++)
                    mma16816(acc[mt][nt], FA[s][mt], FB[s][nt]);
    }
    __syncthreads();   // protect smem reuse by the caller's next tile

    // ---- epilogue ----
    #pragma unroll
    for (int mt = 0; mt < MT; mt++) {
        #pragma unroll
        for (int half = 0; half < 2; half++) {
            int r = m0 + wm + mt * 16 + (lane >> 2) + half * 8;
            #pragma unroll
            for (int nt = 0; nt < 4; nt++) {
                int cc = n0 + wn + nt * 8 + 2 * (lane & 3);
                float v0 = acc[mt][nt][half * 2 + 0];
                float v1 = acc[mt][nt][half * 2 + 1];
                size_t idx = (size_t)r * ldc + cc;
                if (EPI == 0) {
                    *(float2*)(C + idx) = make_float2(v0, v1);
                } else if (EPI == 1) {
                    *(uint32_t*)(Ch + idx) = pack_h2(v0, v1);
                } else if (EPI == 3) {
                    *(float2*)(C + idx) = make_float2(v0, v1);
                    *(uint32_t*)(Ch + idx) = pack_h2(gelu_f(v0), gelu_f(v1));
                } else if (EPI == 4) {
                    float2 a2 = *(const float2*)(aux + idx);
                    *(uint32_t*)(Ch + idx) = pack_h2((v0 - a2.x) * scale, (v1 - a2.y) * scale);
                } else if (EPI == 5) {
                    float2 a2 = *(const float2*)(aux + idx);
                    *(uint32_t*)(Ch + idx) = pack_h2(v0 * gelu_grad_f(a2.x), v1 * gelu_grad_f(a2.y));
                } else if (EPI == 6) {
                    float2 w = *(const float2*)(C + idx);
                    float2 s = *(const float2*)(S + idx);
                    float s0 = decay * s.x - lr * v0;
                    float s1 = decay * s.y - lr * v1;
                    float w0 = om * w.x + s0, w1 = om * w.y + s1;
                    *(float2*)(S + idx) = make_float2(s0, s1);
                    *(float2*)(C + idx) = make_float2(w0, w1);
                    *(uint32_t*)(Ch + idx) = pack_h2(w0, w1);
                } else if (EPI == 7) {
                    int b = r >> 12, sq = r & 4095, chn = sq >> 8, t = sq & 255;
                    size_t orow = (size_t)(chn * 1024 + b * 256 + t) * ldc + cc;
                    *(uint32_t*)(Ch + orow) = pack_h2(v0, v1);
                } else if (EPI == 8) {
                    int b = r >> 12, sq = r & 4095, chn = sq >> 8, t = sq & 255;
                    size_t orow = (size_t)(chn * 1024 + b * 256 + t) * ldc + cc;
                    *(float2*)(C + orow) = make_float2(v0, v1);
                } else { // EPI == 9
                    *(uint32_t*)(Ch + idx) = pack_h2(gelu_f(v0), gelu_f(v1));
                }
            }
        }
    }
}

// ---------------- standalone wrappers ---------------------------------------
__global__ void __launch_bounds__(256) qkv_kernel() {
    extern __shared__ char smem[];
    const uint32_t sbase = smem_u32(smem);
    int m0 = blockIdx.y * 64, n0 = blockIdx.x * 128;
    int z = blockIdx.z;
    if (z == 0)
        tile_gemm<64,false,false,1>(g_xh, D_IN, g_wqh, D_IN, D_IN,
            m0, n0, sbase, nullptr, g_Qh, D_IN, nullptr, 0.f, 0.f, 0.f, 0.f, nullptr);
    else if (z == 1)
        tile_gemm<64,false,false,7>(g_xh, D_IN, g_wkh, D_IN, D_IN,
            m0, n0, sbase, nullptr, g_Kh, D_IN, nullptr, 0.f, 0.f, 0.f, 0.f, nullptr);
    else
        tile_gemm<64,false,false,8>(g_xh, D_IN, g_wvh, D_IN, D_IN,
            m0, n0, sbase, g_V, nullptr, D_IN, nullptr, 0.f, 0.f, 0.f, 0.f, nullptr);
}

__global__ void __launch_bounds__(256) ro1_kernel() {
    extern __shared__ char smem[];
    const uint32_t sbase = smem_u32(smem);
    tile_gemm<64,false,false,9>(g_Qh, D_IN, g_W1h, HID, D_IN,
        blockIdx.y * 64, blockIdx.x * 128, sbase,
        nullptr, g_Hqh, HID, nullptr, 0.f, 0.f, 0.f, 0.f, nullptr);
}

__global__ void __launch_bounds__(256) ro2_kernel(float* __restrict__ out) {
    extern __shared__ char smem[];
    const uint32_t sbase = smem_u32(smem);
    tile_gemm<64,false,false,0>(g_Hqh, HID, g_W2hA, D_IN, HID,
        blockIdx.y * 64, blockIdx.x * 128, sbase,
        out, nullptr, D_IN, nullptr, 0.f, 0.f, 0.f, 0.f, nullptr);
}

// ---------------- software grid barrier --------------------------------------
__device__ __forceinline__ void gsync(unsigned& epoch) {
    __syncthreads();
    if (threadIdx.x == 0) {
        __threadfence();
        epoch++;
        atomicAdd(&g_arrive, 1u);
        const unsigned target = epoch * NB;
        while (__ldcg(&g_arrive) < target) __nanosleep(32);
        __threadfence();
    }
    __syncthreads();
}

// ---------------- persistent chunk loop --------------------------------------
__global__ void __launch_bounds__(256, 1)
chunk_loop(const float* __restrict__ alpha_t, const float* __restrict__ lr_t,
           const float* __restrict__ decay_t, const int* __restrict__ upd)
{
    if (*upd == 0) return;
    const float alpha = sigmoid_f(*alpha_t);
    const float lr    = sigmoid_f(*lr_t);
    const float decay = sigmoid_f(*decay_t);
    const float om    = 1.0f - alpha;
    const float escale = 2.0f / (float)(ROWS_CHUNK * D_IN);

    extern __shared__ char smem[];
    const uint32_t sbase = smem_u32(smem);
    unsigned epoch = 0;

    for (int c = 0; c < NCHUNK; c++) {
        const __half* Kch = g_Kh + (size_t)c * ROWS_CHUNK * D_IN;
        const float*  Vc  = g_V  + (size_t)c * ROWS_CHUNK * D_IN;
        __half* W2cur = (c & 1) ? g_W2hB : g_W2hA;
        __half* W2nxt = (c & 1) ? g_W2hA : g_W2hB;

        // P1: H = Kc @ W1 (f32), Ah = h(gelu(H))      128 tiles BM=64 K=512
        for (int t = blockIdx.x; t < 128; t += NB)
            tile_gemm<64,false,false,3>(Kch, D_IN, g_W1h, HID, D_IN,
                (t >> 3) * 64, (t & 7) * 128, sbase,
                g_H, g_Ah, HID, nullptr, 0.f, 0.f, 0.f, 0.f, nullptr);
        gsync(epoch);

        // P2: Eh = h((A @ W2 - Vc)*escale)            128 tiles BM=32 K=1024
        for (int t = blockIdx.x; t < 128; t += NB)
            tile_gemm<32,false,false,4>(g_Ah, HID, W2cur, D_IN, HID,
                (t >> 2) * 32, (t & 3) * 128, sbase,
                nullptr, g_Eh, D_IN, Vc, escale, 0.f, 0.f, 0.f, nullptr);
        gsync(epoch);

        // P3: dHh = h((E @ W2^T)*gelu'(H))            128 tiles BM=64 K=512
        //     G2 = A^T @ E, fused W2/S2 update -> W2nxt  128 tiles BM=32 K=1024
        for (int t = blockIdx.x; t < 256; t += NB) {
            if (t < 128)
                tile_gemm<64,false,true,5>(g_Eh, D_IN, W2cur, D_IN, D_IN,
                    (t >> 3) * 64, (t & 7) * 128, sbase,
                    nullptr, g_dHh, HID, g_H, 0.f, 0.f, 0.f, 0.f, nullptr);
            else {
                int u = t - 128;
                tile_gemm<32,true,false,6>(g_Ah, HID, g_Eh, D_IN, ROWS_CHUNK,
                    (u >> 2) * 32, (u & 3) * 128, sbase,
                    g_W2, W2nxt, D_IN, nullptr, 0.f, decay, lr, om, g_S2);
            }
        }
        gsync(epoch);

        // P4: G1 = Kc^T @ dH, fused W1/S1 update      128 tiles BM=32 K=1024
        for (int t = blockIdx.x; t < 128; t += NB)
            tile_gemm<32,true,false,6>(Kch, D_IN, g_dHh, HID, ROWS_CHUNK,
                (t >> 3) * 32, (t & 7) * 128, sbase,
                g_W1, g_W1h, HID, nullptr, 0.f, decay, lr, om, g_S1);
        gsync(epoch);
    }
}

// ---------------- init / convert kernels -------------------------------------
__global__ void half_kernel(const float* __restrict__ src, __half* __restrict__ h, int n4) {
    int i = blockIdx.x * 256 + threadIdx.x;
    if (i >= n4) return;
    float4 v = ((const float4*)src)[i];
    ((uint2*)h)[i] = make_uint2(pack_h2(v.x, v.y), pack_h2(v.z, v.w));
}
__global__ void init_kernel(const float* __restrict__ w1, const float* __restrict__ w2) {
    int i = blockIdx.x * 256 + threadIdx.x;
    if (i == 0) g_arrive = 0;
    if (i < WSZ) {
        float a = w1[i], b = w2[i];
        g_W1[i] = a; g_W2[i] = b;
        g_S1[i] = 0.f; g_S2[i] = 0.f;
        g_W1h[i]  = __float2half_rn(a);
        g_W2hA[i] = __float2half_rn(b);
    }
}

// ---------------- launcher ----------------------------------------------------
extern "C" void kernel_launch(void* const* d_in, const int* in_sizes, int n_in,
                              void* d_out, int out_size)
{
    const float* x       = (const float*)d_in[0];
    const float* w_q     = (const float*)d_in[1];
    const float* w_k     = (const float*)d_in[2];
    const float* w_v     = (const float*)d_in[3];
    const float* mem_w1  = (const float*)d_in[4];
    const float* mem_w2  = (const float*)d_in[5];
    const float* alpha_t = (const float*)d_in[6];
    const float* lr_t    = (const float*)d_in[7];
    const float* decay_t = (const float*)d_in[8];
    const int*   upd     = (const int*)d_in[9];
    float* out = (float*)d_out;

    __half *xh, *wqh, *wkh, *wvh;
    cudaGetSymbolAddress((void**)&xh,  g_xh);
    cudaGetSymbolAddress((void**)&wqh, g_wqh);
    cudaGetSymbolAddress((void**)&wkh, g_wkh);
    cudaGetSymbolAddress((void**)&wvh, g_wvh);

    cudaFuncSetAttribute(qkv_kernel, cudaFuncAttributeMaxDynamicSharedMemorySize, P_SMEM);
    cudaFuncSetAttribute(ro1_kernel, cudaFuncAttributeMaxDynamicSharedMemorySize, P_SMEM);
    cudaFuncSetAttribute(ro2_kernel, cudaFuncAttributeMaxDynamicSharedMemorySize, P_SMEM);
    cudaFuncSetAttribute(chunk_loop, cudaFuncAttributeMaxDynamicSharedMemorySize, P_SMEM);

    const dim3 thr(256);

    {
        int n4 = ROWS_TOTAL * D_IN / 4;
        half_kernel<<<(n4 + 255) / 256, thr>>>(x, xh, n4);
        int w4 = D_IN * D_IN / 4;
        half_kernel<<<(w4 + 255) / 256, thr>>>(w_q, wqh, w4);
        half_kernel<<<(w4 + 255) / 256, thr>>>(w_k, wkh, w4);
        half_kernel<<<(w4 + 255) / 256, thr>>>(w_v, wvh, w4);
    }
    init_kernel<<<WSZ / 256, thr>>>(mem_w1, mem_w2);

    qkv_kernel<<<dim3(D_IN / 128, ROWS_TOTAL / 64, 3), thr, P_SMEM>>>();

    chunk_loop<<<NB, thr, P_SMEM>>>(alpha_t, lr_t, decay_t, upd);

    ro1_kernel<<<dim3(HID / 128, ROWS_TOTAL / 64), thr, P_SMEM>>>();
    ro2_kernel<<<dim3(D_IN / 128, ROWS_TOTAL / 64), thr, P_SMEM>>>(out);

    (void)in_sizes; (void)n_in; (void)out_size;
}